// round 1
// baseline (speedup 1.0000x reference)
#include <cuda_runtime.h>

#define B_ 4
#define C_ 256
#define Q_ 256
#define XD_ 64
#define YD_ 32
#define E_ 64
#define H_ 128
#define ALPHA 0.1f

#define PADR 68   // padded row stride (floats), multiple of 4 for float4 alignment
#define NTILES (B_ * C_ * 4)   // 4096 tiles of 64 rows each

// Scratch (static device globals — no runtime allocation)
__device__ float U_scratch[(size_t)B_ * C_ * C_ * E_];   // [B,C(k),C(j),E]
__device__ float P_scratch[(size_t)B_ * C_ * H_];        // [B,C(j),H]

// ---------------------------------------------------------------------------
// Kernel 1: P[b,j,h] = b1[h] + x[b,j,:]·W1[0:64,h] + y[b,j,:]·W1[64:96,h]
// ---------------------------------------------------------------------------
__global__ void p_kernel(const float* __restrict__ x, const float* __restrict__ y,
                         const float* __restrict__ W1, const float* __restrict__ b1) {
    int bj = blockIdx.x;          // 0..B*C-1
    int h  = threadIdx.x;         // 0..127
    const float* xr = x + (size_t)bj * XD_;
    const float* yr = y + (size_t)bj * YD_;
    float acc = b1[h];
    #pragma unroll 8
    for (int d = 0; d < XD_; d++) acc = fmaf(xr[d], W1[d * H_ + h], acc);
    #pragma unroll 8
    for (int d = 0; d < YD_; d++) acc = fmaf(yr[d], W1[(XD_ + d) * H_ + h], acc);
    P_scratch[(size_t)bj * H_ + h] = acc;
}

// ---------------------------------------------------------------------------
// Kernel 2: persistent MLP. Each tile = 64 rows (one (b,k), quarter of j).
// h1 = relu(P + rc·W1e); h2 = relu(h1·W2 + b2); U = h2·W3 + b3.
// Weights staged once per block in smem. Activations kept transposed
// (k-major) in smem so the K-loop reads are conflict-free float4s.
// ---------------------------------------------------------------------------
__global__ void __launch_bounds__(256, 1)
mlp_kernel(const float* __restrict__ rc,
           const float* __restrict__ W1,
           const float* __restrict__ b2v,
           const float* __restrict__ W2,
           const float* __restrict__ W3,
           const float* __restrict__ b3v) {
    extern __shared__ float s[];
    float* W1e = s;                       // [64][128]
    float* W2s = W1e + 64 * H_;           // [128][128]
    float* W3s = W2s + H_ * H_;           // [128][64]
    float* b2s = W3s + H_ * E_;           // [128]
    float* b3s = b2s + H_;                // [64]
    float* inT = b3s + E_;                // [64][PADR]   inT[e][r]
    float* h1T = inT + 64 * PADR;         // [128][PADR]  h1T[h][r]
    float* h2T = h1T + H_ * PADR;         // [128][PADR]

    const int t = threadIdx.x;

    // Stage weights once
    for (int i = t; i < 64 * H_; i += 256) W1e[i] = W1[(96 + (i >> 7)) * H_ + (i & 127)];
    for (int i = t; i < H_ * H_; i += 256) W2s[i] = W2[i];
    for (int i = t; i < H_ * E_; i += 256) W3s[i] = W3[i];
    if (t < H_) b2s[t] = b2v[t];
    if (t < E_) b3s[t] = b3v[t];

    for (int tile = blockIdx.x; tile < NTILES; tile += gridDim.x) {
        const int jsub = tile & 3;
        const int bk   = tile >> 2;       // b*C + k
        const int b    = bk >> 8;         // /C_
        const int j0   = jsub * 64;
        const float* rcin = rc + ((size_t)bk * C_ + j0) * E_;

        __syncthreads();   // protect inT/h1T/h2T reuse across tiles (and weights on iter 0)

        // Load rc tile transposed: inT[e][r] = rc[j0+r][e]
        for (int i = t; i < 64 * 64; i += 256) {
            int r = i >> 6, e = i & 63;
            inT[e * PADR + r] = rcin[(size_t)r * E_ + e];
        }
        __syncthreads();

        // ---- Layer 1: [64r x 128c], K=64 ----
        {
            const int c0 = (t & 31) * 4;
            const int r0 = (t >> 5) * 8;
            float acc[8][4];
            const float* Pp = P_scratch + ((size_t)(b * C_ + j0 + r0)) * H_ + c0;
            #pragma unroll
            for (int rr = 0; rr < 8; rr++) {
                float4 p4 = *(const float4*)(Pp + (size_t)rr * H_);
                acc[rr][0] = p4.x; acc[rr][1] = p4.y; acc[rr][2] = p4.z; acc[rr][3] = p4.w;
            }
            #pragma unroll 2
            for (int kk = 0; kk < 64; kk++) {
                float4 w  = *(const float4*)&W1e[kk * H_ + c0];
                float4 a0 = *(const float4*)&inT[kk * PADR + r0];
                float4 a1 = *(const float4*)&inT[kk * PADR + r0 + 4];
                float av[8] = {a0.x, a0.y, a0.z, a0.w, a1.x, a1.y, a1.z, a1.w};
                #pragma unroll
                for (int rr = 0; rr < 8; rr++) {
                    acc[rr][0] = fmaf(av[rr], w.x, acc[rr][0]);
                    acc[rr][1] = fmaf(av[rr], w.y, acc[rr][1]);
                    acc[rr][2] = fmaf(av[rr], w.z, acc[rr][2]);
                    acc[rr][3] = fmaf(av[rr], w.w, acc[rr][3]);
                }
            }
            #pragma unroll
            for (int rr = 0; rr < 8; rr++)
                #pragma unroll
                for (int cc = 0; cc < 4; cc++)
                    h1T[(c0 + cc) * PADR + r0 + rr] = fmaxf(acc[rr][cc], 0.0f);
        }
        __syncthreads();

        // ---- Layer 2: [64r x 128c], K=128 ----
        {
            const int c0 = (t & 31) * 4;
            const int r0 = (t >> 5) * 8;
            float acc[8][4];
            #pragma unroll
            for (int rr = 0; rr < 8; rr++) {
                acc[rr][0] = b2s[c0];     acc[rr][1] = b2s[c0 + 1];
                acc[rr][2] = b2s[c0 + 2]; acc[rr][3] = b2s[c0 + 3];
            }
            #pragma unroll 2
            for (int kk = 0; kk < H_; kk++) {
                float4 w  = *(const float4*)&W2s[kk * H_ + c0];
                float4 a0 = *(const float4*)&h1T[kk * PADR + r0];
                float4 a1 = *(const float4*)&h1T[kk * PADR + r0 + 4];
                float av[8] = {a0.x, a0.y, a0.z, a0.w, a1.x, a1.y, a1.z, a1.w};
                #pragma unroll
                for (int rr = 0; rr < 8; rr++) {
                    acc[rr][0] = fmaf(av[rr], w.x, acc[rr][0]);
                    acc[rr][1] = fmaf(av[rr], w.y, acc[rr][1]);
                    acc[rr][2] = fmaf(av[rr], w.z, acc[rr][2]);
                    acc[rr][3] = fmaf(av[rr], w.w, acc[rr][3]);
                }
            }
            #pragma unroll
            for (int rr = 0; rr < 8; rr++)
                #pragma unroll
                for (int cc = 0; cc < 4; cc++)
                    h2T[(c0 + cc) * PADR + r0 + rr] = fmaxf(acc[rr][cc], 0.0f);
        }
        __syncthreads();

        // ---- Layer 3: [64r x 64c], K=128, write U to global ----
        {
            const int e0 = (t & 15) * 4;
            const int r0 = (t >> 4) * 4;
            float acc[4][4];
            #pragma unroll
            for (int rr = 0; rr < 4; rr++) {
                acc[rr][0] = b3s[e0];     acc[rr][1] = b3s[e0 + 1];
                acc[rr][2] = b3s[e0 + 2]; acc[rr][3] = b3s[e0 + 3];
            }
            #pragma unroll 2
            for (int kk = 0; kk < H_; kk++) {
                float4 w = *(const float4*)&W3s[kk * E_ + e0];
                float4 a = *(const float4*)&h2T[kk * PADR + r0];
                float av[4] = {a.x, a.y, a.z, a.w};
                #pragma unroll
                for (int rr = 0; rr < 4; rr++) {
                    acc[rr][0] = fmaf(av[rr], w.x, acc[rr][0]);
                    acc[rr][1] = fmaf(av[rr], w.y, acc[rr][1]);
                    acc[rr][2] = fmaf(av[rr], w.z, acc[rr][2]);
                    acc[rr][3] = fmaf(av[rr], w.w, acc[rr][3]);
                }
            }
            float* up = U_scratch + ((size_t)bk * C_ + j0 + r0) * E_ + e0;
            #pragma unroll
            for (int rr = 0; rr < 4; rr++) {
                float4 o;
                o.x = acc[rr][0]; o.y = acc[rr][1]; o.z = acc[rr][2]; o.w = acc[rr][3];
                *(float4*)(up + (size_t)rr * E_) = o;
            }
        }
    }
}

// ---------------------------------------------------------------------------
// Kernel 3: per-(b,k) attention.  Out = resid - ALPHA * (A @ U)
// for A = c_att_map[b] (rows i) and A = q_att_map[b] (rows q).
// ---------------------------------------------------------------------------
__global__ void __launch_bounds__(256, 2)
attn_kernel(const float* __restrict__ rc, const float* __restrict__ rq,
            const float* __restrict__ attc, const float* __restrict__ attq,
            float* __restrict__ out) {
    extern __shared__ float s[];
    float* Us = s;                  // [256][64]
    float* As = Us + C_ * E_;       // [64][PADR]  As[j][i]

    const int bk = blockIdx.x;      // b*C + k
    const int b  = bk >> 8;
    const int t  = threadIdx.x;

    // Load this (b,k)'s U tile (float4 coalesced)
    {
        const float4* Up = (const float4*)(U_scratch + (size_t)bk * C_ * E_);
        float4* Ud = (float4*)Us;
        for (int i = t; i < (C_ * E_) / 4; i += 256) Ud[i] = Up[i];
    }

    const int e0 = (t & 15) * 4;       // 0..60  (e fastest within warp -> coalesced epilogue)
    const int il = (t >> 4) * 4;       // 0..60  local row group

    float* outC = out;
    float* outQ = out + (size_t)B_ * C_ * C_ * E_;

    #pragma unroll 1
    for (int m = 0; m < 2; m++) {
        const float* att   = (m == 0 ? attc : attq) + (size_t)b * C_ * C_;
        const float* resid = (m == 0 ? rc : rq) + (size_t)bk * C_ * E_;
        float* o           = (m == 0 ? outC : outQ) + (size_t)bk * C_ * E_;

        #pragma unroll 1
        for (int isub = 0; isub < 4; isub++) {
            float acc[4][4] = {};
            #pragma unroll 1
            for (int jc = 0; jc < 4; jc++) {
                __syncthreads();   // previous As consumers done
                // Stage As[j][i] = att[isub*64 + i][jc*64 + j], transposed, float4 global reads
                for (int idx = t; idx < 64 * 16; idx += 256) {
                    int i  = idx >> 4;       // 0..63
                    int j4 = idx & 15;       // 0..15
                    float4 a4 = *(const float4*)&att[(size_t)(isub * 64 + i) * C_ + jc * 64 + j4 * 4];
                    As[(j4 * 4 + 0) * PADR + i] = a4.x;
                    As[(j4 * 4 + 1) * PADR + i] = a4.y;
                    As[(j4 * 4 + 2) * PADR + i] = a4.z;
                    As[(j4 * 4 + 3) * PADR + i] = a4.w;
                }
                __syncthreads();
                #pragma unroll 4
                for (int j = 0; j < 64; j++) {
                    float4 a = *(const float4*)&As[j * PADR + il];
                    float4 u = *(const float4*)&Us[(jc * 64 + j) * E_ + e0];
                    float av[4] = {a.x, a.y, a.z, a.w};
                    #pragma unroll
                    for (int ii = 0; ii < 4; ii++) {
                        acc[ii][0] = fmaf(av[ii], u.x, acc[ii][0]);
                        acc[ii][1] = fmaf(av[ii], u.y, acc[ii][1]);
                        acc[ii][2] = fmaf(av[ii], u.z, acc[ii][2]);
                        acc[ii][3] = fmaf(av[ii], u.w, acc[ii][3]);
                    }
                }
            }
            // Epilogue: out = resid - ALPHA*acc   (coalesced float4)
            #pragma unroll
            for (int ii = 0; ii < 4; ii++) {
                int ig = isub * 64 + il + ii;
                float4 r4 = *(const float4*)&resid[(size_t)ig * E_ + e0];
                float4 o4;
                o4.x = r4.x - ALPHA * acc[ii][0];
                o4.y = r4.y - ALPHA * acc[ii][1];
                o4.z = r4.z - ALPHA * acc[ii][2];
                o4.w = r4.w - ALPHA * acc[ii][3];
                *(float4*)&o[(size_t)ig * E_ + e0] = o4;
            }
        }
    }
}

// ---------------------------------------------------------------------------
// Launch
// ---------------------------------------------------------------------------
extern "C" void kernel_launch(void* const* d_in, const int* in_sizes, int n_in,
                              void* d_out, int out_size) {
    const float* x    = (const float*)d_in[0];
    const float* y    = (const float*)d_in[1];
    const float* rc   = (const float*)d_in[2];
    const float* rq   = (const float*)d_in[3];
    const float* attc = (const float*)d_in[4];
    const float* attq = (const float*)d_in[5];
    const float* W1   = (const float*)d_in[6];
    const float* b1   = (const float*)d_in[7];
    const float* W2   = (const float*)d_in[8];
    const float* b2   = (const float*)d_in[9];
    const float* W3   = (const float*)d_in[10];
    const float* b3   = (const float*)d_in[11];
    float* out = (float*)d_out;

    const int MLP_SMEM  = (64 * H_ + H_ * H_ + H_ * E_ + H_ + E_
                           + 64 * PADR + 2 * H_ * PADR) * (int)sizeof(float);   // ~214 KB
    const int ATTN_SMEM = (C_ * E_ + 64 * PADR) * (int)sizeof(float);            // ~81 KB

    cudaFuncSetAttribute(mlp_kernel,  cudaFuncAttributeMaxDynamicSharedMemorySize, MLP_SMEM);
    cudaFuncSetAttribute(attn_kernel, cudaFuncAttributeMaxDynamicSharedMemorySize, ATTN_SMEM);

    p_kernel<<<B_ * C_, H_>>>(x, y, W1, b1);
    mlp_kernel<<<148, 256, MLP_SMEM>>>(rc, W1, b2, W2, W3, b3);
    attn_kernel<<<B_ * C_, 256, ATTN_SMEM>>>(rc, rq, attc, attq, out);
}

// round 2
// speedup vs baseline: 1.3935x; 1.3935x over previous
#include <cuda_runtime.h>

#define B_ 4
#define C_ 256
#define Q_ 256
#define XD_ 64
#define YD_ 32
#define E_ 64
#define H_ 128
#define ALPHA 0.1f

#define PADR 68    // padded row stride for MLP activation tiles (floats, mult of 4)
#define PADA 132   // padded row stride for attn A tile (floats, mult of 4)
#define NTILES (B_ * C_ * 4)   // 4096 tiles of 64 rows each

typedef unsigned long long u64;

// Scratch (static device globals — no runtime allocation)
__device__ float U_scratch[(size_t)B_ * C_ * C_ * E_];   // [B,C(k),C(j),E]
__device__ float P_scratch[(size_t)B_ * C_ * H_];        // [B,C(j),H]

// ---------------- f32x2 helpers ----------------
__device__ __forceinline__ u64 pack2(float lo, float hi) {
    u64 r;
    asm("mov.b64 %0, {%1, %2};" : "=l"(r) : "f"(lo), "f"(hi));
    return r;
}
__device__ __forceinline__ u64 splat2(float v) { return pack2(v, v); }
__device__ __forceinline__ void unpack2(u64 p, float& lo, float& hi) {
    asm("mov.b64 {%0, %1}, %2;" : "=f"(lo), "=f"(hi) : "l"(p));
}
__device__ __forceinline__ void ffma2(u64& d, u64 a, u64 b) {
    asm("fma.rn.f32x2 %0, %1, %2, %0;" : "+l"(d) : "l"(a), "l"(b));
}

// ---------------------------------------------------------------------------
// Kernel 1: P[b,j,h] = b1[h] + x[b,j,:]·W1[0:64,h] + y[b,j,:]·W1[64:96,h]
// ---------------------------------------------------------------------------
__global__ void p_kernel(const float* __restrict__ x, const float* __restrict__ y,
                         const float* __restrict__ W1, const float* __restrict__ b1) {
    int bj = blockIdx.x;          // 0..B*C-1
    int h  = threadIdx.x;         // 0..127
    const float* xr = x + (size_t)bj * XD_;
    const float* yr = y + (size_t)bj * YD_;
    float acc = b1[h];
    #pragma unroll 8
    for (int d = 0; d < XD_; d++) acc = fmaf(xr[d], W1[d * H_ + h], acc);
    #pragma unroll 8
    for (int d = 0; d < YD_; d++) acc = fmaf(yr[d], W1[(XD_ + d) * H_ + h], acc);
    P_scratch[(size_t)bj * H_ + h] = acc;
}

// ---------------------------------------------------------------------------
// Kernel 2: persistent MLP with f32x2-packed FMAs.
// Tile = 64 rows. L1/L2 use column-strided thread mapping (c = (t&31)+32*cc)
// so transposed epilogue stores are only degree-4 conflicted (STS.64).
// Accumulators packed along rows: a-operands load as native f32x2 pairs.
// ---------------------------------------------------------------------------
__global__ void __launch_bounds__(256, 1)
mlp_kernel(const float* __restrict__ rc,
           const float* __restrict__ W1,
           const float* __restrict__ b2v,
           const float* __restrict__ W2,
           const float* __restrict__ W3,
           const float* __restrict__ b3v) {
    extern __shared__ float s[];
    float* W1e = s;                       // [64][128]
    float* W2s = W1e + 64 * H_;           // [128][128]
    float* W3s = W2s + H_ * H_;           // [128][64]
    float* b2s = W3s + H_ * E_;           // [128]
    float* b3s = b2s + H_;                // [64]
    float* inT = b3s + E_;                // [64][PADR]   inT[e][r]
    float* h1T = inT + 64 * PADR;         // [128][PADR]  h1T[h][r]
    float* h2T = h1T + H_ * PADR;         // [128][PADR]

    const int t = threadIdx.x;

    // Stage weights once
    for (int i = t; i < 64 * H_; i += 256) W1e[i] = W1[(96 + (i >> 7)) * H_ + (i & 127)];
    for (int i = t; i < H_ * H_; i += 256) W2s[i] = W2[i];
    for (int i = t; i < H_ * E_; i += 256) W3s[i] = W3[i];
    if (t < H_) b2s[t] = b2v[t];
    if (t < E_) b3s[t] = b3v[t];

    const int c0 = t & 31;          // L1/L2: cols c0, c0+32, c0+64, c0+96
    const int r0 = (t >> 5) * 8;    // L1/L2: rows r0..r0+7 (warp-uniform)

    for (int tile = blockIdx.x; tile < NTILES; tile += gridDim.x) {
        const int jsub = tile & 3;
        const int bk   = tile >> 2;       // b*C + k
        const int b    = bk >> 8;
        const int j0   = jsub * 64;
        const float* rcin = rc + ((size_t)bk * C_ + j0) * E_;

        __syncthreads();   // protect act-buffer reuse across tiles (and weights on iter 0)

        // Load rc tile transposed: inT[e][r] = rc[j0+r][e]
        for (int i = t; i < 64 * 64; i += 256) {
            int r = i >> 6, e = i & 63;
            inT[e * PADR + r] = rcin[(size_t)r * E_ + e];
        }
        __syncthreads();

        // ---- Layer 1: [64r x 128c], K=64 ----
        {
            u64 acc[4][4];
            const float* Pp = P_scratch + ((size_t)(b * C_ + j0 + r0)) * H_ + c0;
            #pragma unroll
            for (int p = 0; p < 4; p++)
                #pragma unroll
                for (int cc = 0; cc < 4; cc++)
                    acc[p][cc] = pack2(Pp[(size_t)(2 * p) * H_ + 32 * cc],
                                       Pp[(size_t)(2 * p + 1) * H_ + 32 * cc]);
            #pragma unroll 4
            for (int kk = 0; kk < 64; kk++) {
                const float* wrow = &W1e[kk * H_ + c0];
                u64 w0 = splat2(wrow[0]),  w1 = splat2(wrow[32]);
                u64 w2 = splat2(wrow[64]), w3 = splat2(wrow[96]);
                ulonglong2 aA = *(const ulonglong2*)&inT[kk * PADR + r0];
                ulonglong2 aB = *(const ulonglong2*)&inT[kk * PADR + r0 + 4];
                u64 ap[4] = {aA.x, aA.y, aB.x, aB.y};
                #pragma unroll
                for (int p = 0; p < 4; p++) {
                    ffma2(acc[p][0], ap[p], w0);
                    ffma2(acc[p][1], ap[p], w1);
                    ffma2(acc[p][2], ap[p], w2);
                    ffma2(acc[p][3], ap[p], w3);
                }
            }
            #pragma unroll
            for (int p = 0; p < 4; p++)
                #pragma unroll
                for (int cc = 0; cc < 4; cc++) {
                    float lo, hi; unpack2(acc[p][cc], lo, hi);
                    float2 v = make_float2(fmaxf(lo, 0.0f), fmaxf(hi, 0.0f));
                    *(float2*)&h1T[(c0 + 32 * cc) * PADR + r0 + 2 * p] = v;
                }
        }
        __syncthreads();

        // ---- Layer 2: [64r x 128c], K=128 ----
        {
            u64 acc[4][4];
            #pragma unroll
            for (int cc = 0; cc < 4; cc++) {
                u64 bsp = splat2(b2s[c0 + 32 * cc]);
                #pragma unroll
                for (int p = 0; p < 4; p++) acc[p][cc] = bsp;
            }
            #pragma unroll 4
            for (int kk = 0; kk < H_; kk++) {
                const float* wrow = &W2s[kk * H_ + c0];
                u64 w0 = splat2(wrow[0]),  w1 = splat2(wrow[32]);
                u64 w2 = splat2(wrow[64]), w3 = splat2(wrow[96]);
                ulonglong2 aA = *(const ulonglong2*)&h1T[kk * PADR + r0];
                ulonglong2 aB = *(const ulonglong2*)&h1T[kk * PADR + r0 + 4];
                u64 ap[4] = {aA.x, aA.y, aB.x, aB.y};
                #pragma unroll
                for (int p = 0; p < 4; p++) {
                    ffma2(acc[p][0], ap[p], w0);
                    ffma2(acc[p][1], ap[p], w1);
                    ffma2(acc[p][2], ap[p], w2);
                    ffma2(acc[p][3], ap[p], w3);
                }
            }
            #pragma unroll
            for (int p = 0; p < 4; p++)
                #pragma unroll
                for (int cc = 0; cc < 4; cc++) {
                    float lo, hi; unpack2(acc[p][cc], lo, hi);
                    float2 v = make_float2(fmaxf(lo, 0.0f), fmaxf(hi, 0.0f));
                    *(float2*)&h2T[(c0 + 32 * cc) * PADR + r0 + 2 * p] = v;
                }
        }
        __syncthreads();

        // ---- Layer 3: [64r x 64c], K=128, write U to global ----
        {
            const int e0 = (t & 15) * 4;
            const int r3 = (t >> 4) * 4;
            u64 acc[2][4];
            #pragma unroll
            for (int cc = 0; cc < 4; cc++) {
                u64 bsp = splat2(b3s[e0 + cc]);
                acc[0][cc] = bsp; acc[1][cc] = bsp;
            }
            #pragma unroll 4
            for (int kk = 0; kk < H_; kk++) {
                float4 w = *(const float4*)&W3s[kk * E_ + e0];
                u64 w0 = splat2(w.x), w1 = splat2(w.y), w2 = splat2(w.z), w3 = splat2(w.w);
                ulonglong2 aA = *(const ulonglong2*)&h2T[kk * PADR + r3];
                u64 ap[2] = {aA.x, aA.y};
                #pragma unroll
                for (int p = 0; p < 2; p++) {
                    ffma2(acc[p][0], ap[p], w0);
                    ffma2(acc[p][1], ap[p], w1);
                    ffma2(acc[p][2], ap[p], w2);
                    ffma2(acc[p][3], ap[p], w3);
                }
            }
            float* up = U_scratch + ((size_t)bk * C_ + j0 + r3) * E_ + e0;
            #pragma unroll
            for (int p = 0; p < 2; p++) {
                float4 olo, ohi;
                unpack2(acc[p][0], olo.x, ohi.x);
                unpack2(acc[p][1], olo.y, ohi.y);
                unpack2(acc[p][2], olo.z, ohi.z);
                unpack2(acc[p][3], olo.w, ohi.w);
                *(float4*)(up + (size_t)(2 * p) * E_)     = olo;
                *(float4*)(up + (size_t)(2 * p + 1) * E_) = ohi;
            }
        }
    }
}

// ---------------------------------------------------------------------------
// Kernel 3: per-(b,k) attention.  Out = resid - ALPHA * (A @ U), f32x2 packed.
// Microtile 8 rows (i) x 4 cols (e); rows packed in f32x2 pairs (native from
// the transposed A tile), U values splatted.
// ---------------------------------------------------------------------------
__global__ void __launch_bounds__(256, 2)
attn_kernel(const float* __restrict__ rc, const float* __restrict__ rq,
            const float* __restrict__ attc, const float* __restrict__ attq,
            float* __restrict__ out) {
    extern __shared__ float s[];
    float* Us = s;                  // [256][64]
    float* As = Us + C_ * E_;       // [64][PADA]  As[j][i], i range 128

    const int bk = blockIdx.x;      // b*C + k
    const int b  = bk >> 8;
    const int t  = threadIdx.x;

    // Load this (b,k)'s U tile (float4 coalesced)
    {
        const float4* Up = (const float4*)(U_scratch + (size_t)bk * C_ * E_);
        float4* Ud = (float4*)Us;
        for (int i = t; i < (C_ * E_) / 4; i += 256) Ud[i] = Up[i];
    }

    const int e0 = (t & 15) * 4;       // 0..60
    const int il = (t >> 4) * 8;       // 0..120 local row group (8 rows)

    float* outC = out;
    float* outQ = out + (size_t)B_ * C_ * C_ * E_;

    #pragma unroll 1
    for (int m = 0; m < 2; m++) {
        const float* att   = (m == 0 ? attc : attq) + (size_t)b * C_ * C_;
        const float* resid = (m == 0 ? rc : rq) + (size_t)bk * C_ * E_;
        float* o           = (m == 0 ? outC : outQ) + (size_t)bk * C_ * E_;

        #pragma unroll 1
        for (int isub = 0; isub < 2; isub++) {     // 128 rows per pass
            u64 acc[4][4];
            #pragma unroll
            for (int p = 0; p < 4; p++)
                #pragma unroll
                for (int cc = 0; cc < 4; cc++) acc[p][cc] = 0ull;

            #pragma unroll 1
            for (int jc = 0; jc < 4; jc++) {
                __syncthreads();   // previous As consumers done
                // Stage As[j][i] = att[isub*128 + i][jc*64 + j] (transposed)
                for (int idx = t; idx < 128 * 16; idx += 256) {
                    int i  = idx >> 4;       // 0..127
                    int j4 = idx & 15;       // 0..15
                    float4 a4 = *(const float4*)&att[(size_t)(isub * 128 + i) * C_ + jc * 64 + j4 * 4];
                    As[(j4 * 4 + 0) * PADA + i] = a4.x;
                    As[(j4 * 4 + 1) * PADA + i] = a4.y;
                    As[(j4 * 4 + 2) * PADA + i] = a4.z;
                    As[(j4 * 4 + 3) * PADA + i] = a4.w;
                }
                __syncthreads();
                #pragma unroll 4
                for (int j = 0; j < 64; j++) {
                    ulonglong2 aA = *(const ulonglong2*)&As[j * PADA + il];
                    ulonglong2 aB = *(const ulonglong2*)&As[j * PADA + il + 4];
                    float4 u = *(const float4*)&Us[(jc * 64 + j) * E_ + e0];
                    u64 u0 = splat2(u.x), u1 = splat2(u.y), u2 = splat2(u.z), u3 = splat2(u.w);
                    u64 ap[4] = {aA.x, aA.y, aB.x, aB.y};
                    #pragma unroll
                    for (int p = 0; p < 4; p++) {
                        ffma2(acc[p][0], ap[p], u0);
                        ffma2(acc[p][1], ap[p], u1);
                        ffma2(acc[p][2], ap[p], u2);
                        ffma2(acc[p][3], ap[p], u3);
                    }
                }
            }
            // Epilogue: out = resid - ALPHA*acc   (coalesced float4, 8 rows)
            #pragma unroll
            for (int p = 0; p < 4; p++) {
                int igA = isub * 128 + il + 2 * p;
                float4 rA = *(const float4*)&resid[(size_t)igA * E_ + e0];
                float4 rB = *(const float4*)&resid[(size_t)(igA + 1) * E_ + e0];
                float lo, hi;
                float4 oA, oB;
                unpack2(acc[p][0], lo, hi); oA.x = rA.x - ALPHA * lo; oB.x = rB.x - ALPHA * hi;
                unpack2(acc[p][1], lo, hi); oA.y = rA.y - ALPHA * lo; oB.y = rB.y - ALPHA * hi;
                unpack2(acc[p][2], lo, hi); oA.z = rA.z - ALPHA * lo; oB.z = rB.z - ALPHA * hi;
                unpack2(acc[p][3], lo, hi); oA.w = rA.w - ALPHA * lo; oB.w = rB.w - ALPHA * hi;
                *(float4*)&o[(size_t)igA * E_ + e0]       = oA;
                *(float4*)&o[(size_t)(igA + 1) * E_ + e0] = oB;
            }
        }
    }
}

// ---------------------------------------------------------------------------
// Launch
// ---------------------------------------------------------------------------
extern "C" void kernel_launch(void* const* d_in, const int* in_sizes, int n_in,
                              void* d_out, int out_size) {
    const float* x    = (const float*)d_in[0];
    const float* y    = (const float*)d_in[1];
    const float* rc   = (const float*)d_in[2];
    const float* rq   = (const float*)d_in[3];
    const float* attc = (const float*)d_in[4];
    const float* attq = (const float*)d_in[5];
    const float* W1   = (const float*)d_in[6];
    const float* b1   = (const float*)d_in[7];
    const float* W2   = (const float*)d_in[8];
    const float* b2   = (const float*)d_in[9];
    const float* W3   = (const float*)d_in[10];
    const float* b3   = (const float*)d_in[11];
    float* out = (float*)d_out;

    const int MLP_SMEM  = (64 * H_ + H_ * H_ + H_ * E_ + H_ + E_
                           + 64 * PADR + 2 * H_ * PADR) * (int)sizeof(float);   // ~214 KB
    const int ATTN_SMEM = (C_ * E_ + 64 * PADA) * (int)sizeof(float);            // ~97 KB

    cudaFuncSetAttribute(mlp_kernel,  cudaFuncAttributeMaxDynamicSharedMemorySize, MLP_SMEM);
    cudaFuncSetAttribute(attn_kernel, cudaFuncAttributeMaxDynamicSharedMemorySize, ATTN_SMEM);

    p_kernel<<<B_ * C_, H_>>>(x, y, W1, b1);
    mlp_kernel<<<148, 256, MLP_SMEM>>>(rc, W1, b2, W2, W3, b3);
    attn_kernel<<<B_ * C_, 256, ATTN_SMEM>>>(rc, rq, attc, attq, out);
}

// round 4
// speedup vs baseline: 1.7441x; 1.2516x over previous
#include <cuda_runtime.h>
#include <cstdint>

#define B_ 4
#define C_ 256
#define Q_ 256
#define XD_ 64
#define YD_ 32
#define E_ 64
#define H_ 128
#define ALPHA 0.1f

#define PADR 68
#define NTILES (B_ * C_ * 4)

typedef unsigned long long u64;

// Scratch (static device globals — no runtime allocation)
__device__ float U_scratch[(size_t)B_ * C_ * C_ * E_];   // [B,C(k),C(j),E]
__device__ float P_scratch[(size_t)B_ * C_ * H_];        // [B,C(j),H]

// ---------------- f32x2 helpers ----------------
__device__ __forceinline__ u64 pack2(float lo, float hi) {
    u64 r;
    asm("mov.b64 %0, {%1, %2};" : "=l"(r) : "f"(lo), "f"(hi));
    return r;
}
__device__ __forceinline__ u64 splat2(float v) { return pack2(v, v); }
__device__ __forceinline__ void unpack2(u64 p, float& lo, float& hi) {
    asm("mov.b64 {%0, %1}, %2;" : "=f"(lo), "=f"(hi) : "l"(p));
}
__device__ __forceinline__ void ffma2(u64& d, u64 a, u64 b) {
    asm("fma.rn.f32x2 %0, %1, %2, %0;" : "+l"(d) : "l"(a), "l"(b));
}

// ---------------- mma.sync tf32 helpers (compute_80 features only) ----------
__device__ __forceinline__ uint32_t f2tf32(float f) {
    uint32_t r;
    asm("cvt.rna.tf32.f32 %0, %1;" : "=r"(r) : "f"(f));
    return r;
}
__device__ __forceinline__ void mma_tf32(float d[4], const uint32_t a[4], const uint32_t b[2]) {
    asm volatile(
        "mma.sync.aligned.m16n8k8.row.col.f32.tf32.tf32.f32 "
        "{%0,%1,%2,%3}, {%4,%5,%6,%7}, {%8,%9}, {%0,%1,%2,%3};"
        : "+f"(d[0]), "+f"(d[1]), "+f"(d[2]), "+f"(d[3])
        : "r"(a[0]), "r"(a[1]), "r"(a[2]), "r"(a[3]), "r"(b[0]), "r"(b[1]));
}

// ---------------------------------------------------------------------------
// Kernel 1: P[b,j,h] = b1[h] + x[b,j,:]·W1[0:64,h] + y[b,j,:]·W1[64:96,h]
// ---------------------------------------------------------------------------
__global__ void p_kernel(const float* __restrict__ x, const float* __restrict__ y,
                         const float* __restrict__ W1, const float* __restrict__ b1) {
    int bj = blockIdx.x;
    int h  = threadIdx.x;
    const float* xr = x + (size_t)bj * XD_;
    const float* yr = y + (size_t)bj * YD_;
    float acc = b1[h];
    #pragma unroll 8
    for (int d = 0; d < XD_; d++) acc = fmaf(xr[d], W1[d * H_ + h], acc);
    #pragma unroll 8
    for (int d = 0; d < YD_; d++) acc = fmaf(yr[d], W1[(XD_ + d) * H_ + h], acc);
    P_scratch[(size_t)bj * H_ + h] = acc;
}

// ---------------------------------------------------------------------------
// Kernel 2: persistent MLP (f32x2 packed, unchanged from R2 passing version)
// ---------------------------------------------------------------------------
__global__ void __launch_bounds__(256, 1)
mlp_kernel(const float* __restrict__ rc,
           const float* __restrict__ W1,
           const float* __restrict__ b2v,
           const float* __restrict__ W2,
           const float* __restrict__ W3,
           const float* __restrict__ b3v) {
    extern __shared__ float s[];
    float* W1e = s;
    float* W2s = W1e + 64 * H_;
    float* W3s = W2s + H_ * H_;
    float* b2s = W3s + H_ * E_;
    float* b3s = b2s + H_;
    float* inT = b3s + E_;
    float* h1T = inT + 64 * PADR;
    float* h2T = h1T + H_ * PADR;

    const int t = threadIdx.x;

    for (int i = t; i < 64 * H_; i += 256) W1e[i] = W1[(96 + (i >> 7)) * H_ + (i & 127)];
    for (int i = t; i < H_ * H_; i += 256) W2s[i] = W2[i];
    for (int i = t; i < H_ * E_; i += 256) W3s[i] = W3[i];
    if (t < H_) b2s[t] = b2v[t];
    if (t < E_) b3s[t] = b3v[t];

    const int c0 = t & 31;
    const int r0 = (t >> 5) * 8;

    for (int tile = blockIdx.x; tile < NTILES; tile += gridDim.x) {
        const int jsub = tile & 3;
        const int bk   = tile >> 2;
        const int b    = bk >> 8;
        const int j0   = jsub * 64;
        const float* rcin = rc + ((size_t)bk * C_ + j0) * E_;

        __syncthreads();

        for (int i = t; i < 64 * 64; i += 256) {
            int r = i >> 6, e = i & 63;
            inT[e * PADR + r] = rcin[(size_t)r * E_ + e];
        }
        __syncthreads();

        // ---- Layer 1 ----
        {
            u64 acc[4][4];
            const float* Pp = P_scratch + ((size_t)(b * C_ + j0 + r0)) * H_ + c0;
            #pragma unroll
            for (int p = 0; p < 4; p++)
                #pragma unroll
                for (int cc = 0; cc < 4; cc++)
                    acc[p][cc] = pack2(Pp[(size_t)(2 * p) * H_ + 32 * cc],
                                       Pp[(size_t)(2 * p + 1) * H_ + 32 * cc]);
            #pragma unroll 4
            for (int kk = 0; kk < 64; kk++) {
                const float* wrow = &W1e[kk * H_ + c0];
                u64 w0 = splat2(wrow[0]),  w1 = splat2(wrow[32]);
                u64 w2 = splat2(wrow[64]), w3 = splat2(wrow[96]);
                ulonglong2 aA = *(const ulonglong2*)&inT[kk * PADR + r0];
                ulonglong2 aB = *(const ulonglong2*)&inT[kk * PADR + r0 + 4];
                u64 ap[4] = {aA.x, aA.y, aB.x, aB.y};
                #pragma unroll
                for (int p = 0; p < 4; p++) {
                    ffma2(acc[p][0], ap[p], w0);
                    ffma2(acc[p][1], ap[p], w1);
                    ffma2(acc[p][2], ap[p], w2);
                    ffma2(acc[p][3], ap[p], w3);
                }
            }
            #pragma unroll
            for (int p = 0; p < 4; p++)
                #pragma unroll
                for (int cc = 0; cc < 4; cc++) {
                    float lo, hi; unpack2(acc[p][cc], lo, hi);
                    float2 v = make_float2(fmaxf(lo, 0.0f), fmaxf(hi, 0.0f));
                    *(float2*)&h1T[(c0 + 32 * cc) * PADR + r0 + 2 * p] = v;
                }
        }
        __syncthreads();

        // ---- Layer 2 ----
        {
            u64 acc[4][4];
            #pragma unroll
            for (int cc = 0; cc < 4; cc++) {
                u64 bsp = splat2(b2s[c0 + 32 * cc]);
                #pragma unroll
                for (int p = 0; p < 4; p++) acc[p][cc] = bsp;
            }
            #pragma unroll 4
            for (int kk = 0; kk < H_; kk++) {
                const float* wrow = &W2s[kk * H_ + c0];
                u64 w0 = splat2(wrow[0]),  w1 = splat2(wrow[32]);
                u64 w2 = splat2(wrow[64]), w3 = splat2(wrow[96]);
                ulonglong2 aA = *(const ulonglong2*)&h1T[kk * PADR + r0];
                ulonglong2 aB = *(const ulonglong2*)&h1T[kk * PADR + r0 + 4];
                u64 ap[4] = {aA.x, aA.y, aB.x, aB.y};
                #pragma unroll
                for (int p = 0; p < 4; p++) {
                    ffma2(acc[p][0], ap[p], w0);
                    ffma2(acc[p][1], ap[p], w1);
                    ffma2(acc[p][2], ap[p], w2);
                    ffma2(acc[p][3], ap[p], w3);
                }
            }
            #pragma unroll
            for (int p = 0; p < 4; p++)
                #pragma unroll
                for (int cc = 0; cc < 4; cc++) {
                    float lo, hi; unpack2(acc[p][cc], lo, hi);
                    float2 v = make_float2(fmaxf(lo, 0.0f), fmaxf(hi, 0.0f));
                    *(float2*)&h2T[(c0 + 32 * cc) * PADR + r0 + 2 * p] = v;
                }
        }
        __syncthreads();

        // ---- Layer 3 ----
        {
            const int e0 = (t & 15) * 4;
            const int r3 = (t >> 4) * 4;
            u64 acc[2][4];
            #pragma unroll
            for (int cc = 0; cc < 4; cc++) {
                u64 bsp = splat2(b3s[e0 + cc]);
                acc[0][cc] = bsp; acc[1][cc] = bsp;
            }
            #pragma unroll 4
            for (int kk = 0; kk < H_; kk++) {
                float4 w = *(const float4*)&W3s[kk * E_ + e0];
                u64 w0 = splat2(w.x), w1 = splat2(w.y), w2 = splat2(w.z), w3 = splat2(w.w);
                ulonglong2 aA = *(const ulonglong2*)&h2T[kk * PADR + r3];
                u64 ap[2] = {aA.x, aA.y};
                #pragma unroll
                for (int p = 0; p < 2; p++) {
                    ffma2(acc[p][0], ap[p], w0);
                    ffma2(acc[p][1], ap[p], w1);
                    ffma2(acc[p][2], ap[p], w2);
                    ffma2(acc[p][3], ap[p], w3);
                }
            }
            float* up = U_scratch + ((size_t)bk * C_ + j0 + r3) * E_ + e0;
            #pragma unroll
            for (int p = 0; p < 2; p++) {
                float4 olo, ohi;
                unpack2(acc[p][0], olo.x, ohi.x);
                unpack2(acc[p][1], olo.y, ohi.y);
                unpack2(acc[p][2], olo.z, ohi.z);
                unpack2(acc[p][3], olo.w, ohi.w);
                *(float4*)(up + (size_t)(2 * p) * E_)     = olo;
                *(float4*)(up + (size_t)(2 * p + 1) * E_) = ohi;
            }
        }
    }
}

// ---------------------------------------------------------------------------
// Kernel 3: mma.sync tf32 attention.
//   Grid = b(4) x map(2) x Mquarter(4) x kgroup(16) = 512 CTAs.
//   A = att[b,map] M-slice [64 x 256], staged ONCE, pre-cvt tf32,
//       fragment-major: [mt4][kt32][slot4][lane32] (512B per m16k8 tile).
//   Per k in group (16): B = U[b,k] [256j x 64e] staged raw with bank swizzle
//       [kt32][s2][ (nt*32+lane)^(nt<<2) ]; cvt to tf32 at load.
//   D[64 x 64] per k; epilogue out = resid - ALPHA*D. LDG prefetch of next
//   k's U overlaps the mma loop.
// ---------------------------------------------------------------------------
#define AT_A 0
#define AT_B (64 * 1024)
#define AT_SMEM (128 * 1024)

__global__ void __launch_bounds__(256, 1)
attn_mma_kernel(const float* __restrict__ rc, const float* __restrict__ rq,
                const float* __restrict__ attc, const float* __restrict__ attq,
                float* __restrict__ out) {
    extern __shared__ char smem[];
    const int t = threadIdx.x;
    const int x = blockIdx.x;
    const int kg  = x & 15;
    const int Mq  = (x >> 4) & 3;
    const int map = (x >> 6) & 1;
    const int b   = x >> 7;

    const int wid  = t >> 5;
    const int lane = t & 31;
    const int wm = wid >> 2;      // 2 M-groups of 32 rows
    const int wn = wid & 3;       // 4 N-groups of 16 cols

    // ---- Stage A once: att rows [Mq*64, Mq*64+64), all 256 j, tf32 frag-major
    {
        const float* att = (map ? attq : attc) + (size_t)b * C_ * C_ + (size_t)(Mq * 64) * C_;
        #pragma unroll 4
        for (int it = 0; it < 16; it++) {
            int idx = it * 256 + t;           // 0..4095 float4 chunks
            int i  = idx >> 6;                // 0..63
            int j0 = (idx & 63) * 4;          // 0..252
            float4 v = *(const float4*)&att[(size_t)i * C_ + j0];
            uint4 p;
            p.x = f2tf32(v.x); p.y = f2tf32(v.y); p.z = f2tf32(v.z); p.w = f2tf32(v.w);
            int mt = i >> 4, kt = j0 >> 3;
            int sl = ((i >> 3) & 1) | (((j0 >> 2) & 1) << 1);
            uint32_t off = (uint32_t)(((mt * 32 + kt) * 4 + sl) * 128 + (i & 7) * 16);
            *(uint4*)(smem + AT_A + off) = p;
        }
    }

    float* outbase = out + (map ? (size_t)B_ * C_ * C_ * E_ : 0);
    const float* residbase = map ? rq : rc;

    // B stage helpers (inline, 16 float4 per thread covering 256x64)
    float4 pre[16];
    const int pj  = t >> 4;            // base j row group: thread covers j = pj + 16*it? no:
    // idx scheme: idx = it*256 + t; j = idx>>4 (0..255), e0 = (idx&15)*4

    int k0 = kg * 16;
    {   // prologue: load + store k0
        const float* Ub = U_scratch + ((size_t)(b * C_ + k0)) * C_ * E_;
        #pragma unroll
        for (int it = 0; it < 16; it++) {
            int idx = it * 256 + t;
            int j = idx >> 4, e0 = (idx & 15) * 4;
            pre[it] = *(const float4*)&Ub[(size_t)j * E_ + e0];
        }
        #pragma unroll
        for (int it = 0; it < 16; it++) {
            int idx = it * 256 + t;
            int j = idx >> 4, e0 = (idx & 15) * 4;
            int kt = j >> 3, s2 = (j >> 2) & 1;
            float vv[4] = {pre[it].x, pre[it].y, pre[it].z, pre[it].w};
            #pragma unroll
            for (int r = 0; r < 4; r++) {
                int e = e0 + r;
                int nt = e >> 3;
                int ln = ((e & 7) << 2) | (j & 3);
                int Fp = (nt * 32 + ln) ^ (nt << 2);
                *(float*)(smem + AT_B + ((kt * 2 + s2) << 10) + Fp * 4) = vv[r];
            }
        }
    }
    __syncthreads();

    #pragma unroll 1
    for (int kk = 0; kk < 16; kk++) {
        const int k = k0 + kk;

        // prefetch next k's U into registers (overlaps mma below)
        if (kk < 15) {
            const float* Ub = U_scratch + ((size_t)(b * C_ + k + 1)) * C_ * E_;
            #pragma unroll
            for (int it = 0; it < 16; it++) {
                int idx = it * 256 + t;
                int j = idx >> 4, e0 = (idx & 15) * 4;
                pre[it] = *(const float4*)&Ub[(size_t)j * E_ + e0];
            }
        }

        // ---- mma mainloop: D[64x64] += A[64x256] * B[256x64] ----
        float d[2][2][4];
        #pragma unroll
        for (int i0 = 0; i0 < 2; i0++)
            #pragma unroll
            for (int i1 = 0; i1 < 2; i1++)
                #pragma unroll
                for (int i2 = 0; i2 < 4; i2++) d[i0][i1][i2] = 0.0f;

        #pragma unroll 4
        for (int kt = 0; kt < 32; kt++) {
            uint32_t a[2][4];
            #pragma unroll
            for (int mtl = 0; mtl < 2; mtl++) {
                int mt = wm * 2 + mtl;
                const char* base = smem + AT_A + ((mt * 32 + kt) * 4) * 128 + lane * 4;
                a[mtl][0] = *(const uint32_t*)(base);
                a[mtl][1] = *(const uint32_t*)(base + 128);
                a[mtl][2] = *(const uint32_t*)(base + 256);
                a[mtl][3] = *(const uint32_t*)(base + 384);
            }
            uint32_t bf[2][2];
            #pragma unroll
            for (int ntl = 0; ntl < 2; ntl++) {
                int nt = wn * 2 + ntl;
                int Fp = ((nt * 32 + lane) ^ (nt << 2)) * 4;
                float b0 = *(const float*)(smem + AT_B + ((kt * 2 + 0) << 10) + Fp);
                float b1 = *(const float*)(smem + AT_B + ((kt * 2 + 1) << 10) + Fp);
                bf[ntl][0] = f2tf32(b0);
                bf[ntl][1] = f2tf32(b1);
            }
            #pragma unroll
            for (int mtl = 0; mtl < 2; mtl++)
                #pragma unroll
                for (int ntl = 0; ntl < 2; ntl++)
                    mma_tf32(d[mtl][ntl], a[mtl], bf[ntl]);
        }
        __syncthreads();   // mma reads done; B buffer safe to overwrite

        // store prefetched next-k B to smem
        if (kk < 15) {
            #pragma unroll
            for (int it = 0; it < 16; it++) {
                int idx = it * 256 + t;
                int j = idx >> 4, e0 = (idx & 15) * 4;
                int kt = j >> 3, s2 = (j >> 2) & 1;
                float vv[4] = {pre[it].x, pre[it].y, pre[it].z, pre[it].w};
                #pragma unroll
                for (int r = 0; r < 4; r++) {
                    int e = e0 + r;
                    int nt = e >> 3;
                    int ln = ((e & 7) << 2) | (j & 3);
                    int Fp = (nt * 32 + ln) ^ (nt << 2);
                    *(float*)(smem + AT_B + ((kt * 2 + s2) << 10) + Fp * 4) = vv[r];
                }
            }
        }

        // ---- epilogue: out = resid - ALPHA * D  (gmem only) ----
        {
            const float* resid = residbase + ((size_t)(b * C_ + k) * C_) * E_;
            float* o = outbase + ((size_t)(b * C_ + k) * C_) * E_;
            #pragma unroll
            for (int mtl = 0; mtl < 2; mtl++) {
                int row = Mq * 64 + wm * 32 + mtl * 16 + (lane >> 2);
                #pragma unroll
                for (int ntl = 0; ntl < 2; ntl++) {
                    int e = wn * 16 + ntl * 8 + (lane & 3) * 2;
                    float2 rA = *(const float2*)&resid[(size_t)row * E_ + e];
                    float2 rB = *(const float2*)&resid[(size_t)(row + 8) * E_ + e];
                    float2 oA, oB;
                    oA.x = rA.x - ALPHA * d[mtl][ntl][0];
                    oA.y = rA.y - ALPHA * d[mtl][ntl][1];
                    oB.x = rB.x - ALPHA * d[mtl][ntl][2];
                    oB.y = rB.y - ALPHA * d[mtl][ntl][3];
                    *(float2*)&o[(size_t)row * E_ + e]       = oA;
                    *(float2*)&o[(size_t)(row + 8) * E_ + e] = oB;
                }
            }
        }

        if (kk < 15) __syncthreads();   // B stores visible before next mma
    }
}

// ---------------------------------------------------------------------------
// Launch
// ---------------------------------------------------------------------------
extern "C" void kernel_launch(void* const* d_in, const int* in_sizes, int n_in,
                              void* d_out, int out_size) {
    const float* x    = (const float*)d_in[0];
    const float* y    = (const float*)d_in[1];
    const float* rc   = (const float*)d_in[2];
    const float* rq   = (const float*)d_in[3];
    const float* attc = (const float*)d_in[4];
    const float* attq = (const float*)d_in[5];
    const float* W1   = (const float*)d_in[6];
    const float* b1   = (const float*)d_in[7];
    const float* W2   = (const float*)d_in[8];
    const float* b2   = (const float*)d_in[9];
    const float* W3   = (const float*)d_in[10];
    const float* b3   = (const float*)d_in[11];
    float* out = (float*)d_out;

    const int MLP_SMEM = (64 * H_ + H_ * H_ + H_ * E_ + H_ + E_
                          + 64 * PADR + 2 * H_ * PADR) * (int)sizeof(float);

    cudaFuncSetAttribute(mlp_kernel,      cudaFuncAttributeMaxDynamicSharedMemorySize, MLP_SMEM);
    cudaFuncSetAttribute(attn_mma_kernel, cudaFuncAttributeMaxDynamicSharedMemorySize, AT_SMEM);

    p_kernel<<<B_ * C_, H_>>>(x, y, W1, b1);
    mlp_kernel<<<148, 256, MLP_SMEM>>>(rc, W1, b2, W2, W3, b3);
    attn_mma_kernel<<<512, 256, AT_SMEM>>>(rc, rq, attc, attq, out);
}

// round 5
// speedup vs baseline: 2.7076x; 1.5525x over previous
#include <cuda_runtime.h>
#include <cstdint>

#define B_ 4
#define C_ 256
#define Q_ 256
#define XD_ 64
#define YD_ 32
#define E_ 64
#define H_ 128
#define ALPHA 0.1f

#define NTILES (B_ * C_ * 4)

typedef unsigned long long u64;

// Scratch (static device globals — no runtime allocation)
__device__ float U_scratch[(size_t)B_ * C_ * C_ * E_];   // [B,C(k),C(j),E]
__device__ float P_scratch[(size_t)B_ * C_ * H_];        // [B,C(j),H]

// ---------------- mma.sync tf32 helpers (compute_80 features only) ----------
__device__ __forceinline__ uint32_t f2tf32(float f) {
    uint32_t r;
    asm("cvt.rna.tf32.f32 %0, %1;" : "=r"(r) : "f"(f));
    return r;
}
__device__ __forceinline__ void mma_tf32(float d[4], const uint32_t a[4], const uint32_t b[2]) {
    asm volatile(
        "mma.sync.aligned.m16n8k8.row.col.f32.tf32.tf32.f32 "
        "{%0,%1,%2,%3}, {%4,%5,%6,%7}, {%8,%9}, {%0,%1,%2,%3};"
        : "+f"(d[0]), "+f"(d[1]), "+f"(d[2]), "+f"(d[3])
        : "r"(a[0]), "r"(a[1]), "r"(a[2]), "r"(a[3]), "r"(b[0]), "r"(b[1]));
}

// ---------------------------------------------------------------------------
// Kernel 1: P[b,j,h] = b1[h] + x[b,j,:]·W1[0:64,h] + y[b,j,:]·W1[64:96,h]
// ---------------------------------------------------------------------------
__global__ void p_kernel(const float* __restrict__ x, const float* __restrict__ y,
                         const float* __restrict__ W1, const float* __restrict__ b1) {
    int bj = blockIdx.x;
    int h  = threadIdx.x;
    const float* xr = x + (size_t)bj * XD_;
    const float* yr = y + (size_t)bj * YD_;
    float acc = b1[h];
    #pragma unroll 8
    for (int d = 0; d < XD_; d++) acc = fmaf(xr[d], W1[d * H_ + h], acc);
    #pragma unroll 8
    for (int d = 0; d < YD_; d++) acc = fmaf(yr[d], W1[(XD_ + d) * H_ + h], acc);
    P_scratch[(size_t)bj * H_ + h] = acc;
}

// ---------------------------------------------------------------------------
// Kernel 2: persistent tensor-core MLP (mma.sync tf32).
//   Tile = 64 rows (one (b,k), quarter of j). 8 warps: wm=wid>>2 (2 M-groups
//   of 32 rows), wn=wid&3 (4 N-groups). Weights staged once, fragment-major.
//   Activations pass between layers via smem A-fragment-major (stride 516B).
// ---------------------------------------------------------------------------
// smem byte offsets
#define W1F   0                       // 16nt x 8kt  x 256B = 32768
#define W2F   32768                   // 16nt x 16kt x 256B = 65536
#define W3F   98304                   // 8nt  x 16kt x 256B = 32768
#define B2S   131072                  // 128 floats
#define B3S   131584                  // 64 floats
#define AFS   516                     // A-frag stride (512 + 4 pad)
#define INF   131840                  // 32 frags  x 516 = 16512
#define H1F   148352                  // 64 frags  x 516 = 33024
#define H2F   181376                  // 64 frags  x 516 = 33024
#define MLP_SMEM_B 214400

__global__ void __launch_bounds__(256, 1)
mlp_tc_kernel(const float* __restrict__ rc,
              const float* __restrict__ W1,
              const float* __restrict__ b2v,
              const float* __restrict__ W2,
              const float* __restrict__ W3,
              const float* __restrict__ b3v) {
    extern __shared__ char smem[];
    const int t    = threadIdx.x;
    const int wid  = t >> 5;
    const int lane = t & 31;
    const int wm   = wid >> 2;     // 0..1
    const int wn   = wid & 3;      // 0..3

    // ---- Stage weights fragment-major (once) ----
    for (int i = t; i < 64 * 128; i += 256) {           // W1e rows 96..159
        int k = i >> 7, n = i & 127;
        uint32_t v = f2tf32(W1[(96 + k) * H_ + n]);
        int fr = (n >> 3) * 8 + (k >> 3);
        uint32_t off = W1F + (fr << 8) + ((((n & 7) << 2) | (k & 3)) << 3) + (((k >> 3) & 0) << 2) + ((k & 7) >> 2 << 2);
        *(uint32_t*)(smem + off) = v;
    }
    for (int i = t; i < 128 * 128; i += 256) {
        int k = i >> 7, n = i & 127;
        uint32_t v = f2tf32(W2[(size_t)k * H_ + n]);
        int fr = (n >> 3) * 16 + (k >> 3);
        uint32_t off = W2F + (fr << 8) + ((((n & 7) << 2) | (k & 3)) << 3) + (((k & 7) >> 2) << 2);
        *(uint32_t*)(smem + off) = v;
    }
    for (int i = t; i < 128 * 64; i += 256) {
        int k = i >> 6, n = i & 63;
        uint32_t v = f2tf32(W3[(size_t)k * E_ + n]);
        int fr = (n >> 3) * 16 + (k >> 3);
        uint32_t off = W3F + (fr << 8) + ((((n & 7) << 2) | (k & 3)) << 3) + (((k & 7) >> 2) << 2);
        *(uint32_t*)(smem + off) = v;
    }
    if (t < 128) *(float*)(smem + B2S + t * 4) = b2v[t];
    if (t < 64)  *(float*)(smem + B3S + t * 4) = b3v[t];
    __syncthreads();

    for (int tile = blockIdx.x; tile < NTILES; tile += gridDim.x) {
        const int jsub = tile & 3;
        const int bk   = tile >> 2;
        const int b    = bk >> 8;
        const int j0   = jsub * 64;

        // ---- Stage input rc tile as A-fragments (tf32) ----
        {
            const float* rcin = rc + ((size_t)bk * C_ + j0) * E_;
            #pragma unroll
            for (int it = 0; it < 4; it++) {
                int idx = it * 256 + t;
                int r = idx >> 4, e4 = idx & 15;
                float4 v = *(const float4*)&rcin[(size_t)r * E_ + e4 * 4];
                float vv[4] = {v.x, v.y, v.z, v.w};
                #pragma unroll
                for (int c = 0; c < 4; c++) {
                    int e = e4 * 4 + c;
                    int mt = r >> 4, kt = e >> 3;
                    int slot  = ((r >> 3) & 1) | (((e >> 2) & 1) << 1);
                    int lane2 = ((r & 7) << 2) | (e & 3);
                    uint32_t off = INF + (mt * 8 + kt) * AFS + slot * 128 + lane2 * 4;
                    *(uint32_t*)(smem + off) = f2tf32(vv[c]);
                }
            }
        }
        __syncthreads();

        // ---- Layer 1: h1[64x128] = relu(P + in @ W1e), K=64 ----
        {
            float d[2][4][4];
            const float* Pp = P_scratch + (size_t)(b * C_ + j0) * H_;
            #pragma unroll
            for (int mtl = 0; mtl < 2; mtl++) {
                int r0 = wm * 32 + mtl * 16 + (lane >> 2);
                #pragma unroll
                for (int ntl = 0; ntl < 4; ntl++) {
                    int col = wn * 32 + ntl * 8 + (lane & 3) * 2;
                    float2 p0 = *(const float2*)&Pp[(size_t)r0 * H_ + col];
                    float2 p1 = *(const float2*)&Pp[(size_t)(r0 + 8) * H_ + col];
                    d[mtl][ntl][0] = p0.x; d[mtl][ntl][1] = p0.y;
                    d[mtl][ntl][2] = p1.x; d[mtl][ntl][3] = p1.y;
                }
            }
            #pragma unroll
            for (int kt = 0; kt < 8; kt++) {
                uint32_t a[2][4];
                #pragma unroll
                for (int mtl = 0; mtl < 2; mtl++) {
                    const char* base = smem + INF + ((wm * 2 + mtl) * 8 + kt) * AFS + lane * 4;
                    a[mtl][0] = *(const uint32_t*)(base);
                    a[mtl][1] = *(const uint32_t*)(base + 128);
                    a[mtl][2] = *(const uint32_t*)(base + 256);
                    a[mtl][3] = *(const uint32_t*)(base + 384);
                }
                #pragma unroll
                for (int ntl = 0; ntl < 4; ntl++) {
                    int nt = wn * 4 + ntl;
                    uint2 wv = *(const uint2*)(smem + W1F + ((nt * 8 + kt) << 8) + lane * 8);
                    uint32_t bw[2] = {wv.x, wv.y};
                    #pragma unroll
                    for (int mtl = 0; mtl < 2; mtl++) mma_tf32(d[mtl][ntl], a[mtl], bw);
                }
            }
            // relu + cvt + store as A-frags for layer 2
            #pragma unroll
            for (int mtl = 0; mtl < 2; mtl++) {
                int mt = wm * 2 + mtl;
                int rlo = (lane >> 2);
                #pragma unroll
                for (int ntl = 0; ntl < 4; ntl++) {
                    int kt = wn * 4 + ntl;                 // col>>3
                    int c0 = (lane & 3) * 2;               // col within 8: c0, c0+1
                    const char* fb = smem + H1F + (mt * 16 + kt) * AFS;
                    #pragma unroll
                    for (int q = 0; q < 4; q++) {
                        int row8  = (q >> 1);              // 0: rows rlo, 1: rlo+8
                        int cadd  = (q & 1);
                        int col   = c0 + cadd;
                        int slot  = row8 | (((col >> 2) & 1) << 1);
                        int lane2 = ((rlo & 7) << 2) | (col & 3);
                        float v = fmaxf(d[mtl][ntl][q], 0.0f);
                        *(uint32_t*)(fb + slot * 128 + lane2 * 4) = f2tf32(v);
                    }
                }
            }
        }
        __syncthreads();

        // ---- Layer 2: h2[64x128] = relu(h1 @ W2 + b2), K=128 ----
        {
            float d[2][4][4];
            #pragma unroll
            for (int mtl = 0; mtl < 2; mtl++)
                #pragma unroll
                for (int ntl = 0; ntl < 4; ntl++) {
                    int col = wn * 32 + ntl * 8 + (lane & 3) * 2;
                    float2 bb = *(const float2*)(smem + B2S + col * 4);
                    d[mtl][ntl][0] = bb.x; d[mtl][ntl][1] = bb.y;
                    d[mtl][ntl][2] = bb.x; d[mtl][ntl][3] = bb.y;
                }
            #pragma unroll 8
            for (int kt = 0; kt < 16; kt++) {
                uint32_t a[2][4];
                #pragma unroll
                for (int mtl = 0; mtl < 2; mtl++) {
                    const char* base = smem + H1F + ((wm * 2 + mtl) * 16 + kt) * AFS + lane * 4;
                    a[mtl][0] = *(const uint32_t*)(base);
                    a[mtl][1] = *(const uint32_t*)(base + 128);
                    a[mtl][2] = *(const uint32_t*)(base + 256);
                    a[mtl][3] = *(const uint32_t*)(base + 384);
                }
                #pragma unroll
                for (int ntl = 0; ntl < 4; ntl++) {
                    int nt = wn * 4 + ntl;
                    uint2 wv = *(const uint2*)(smem + W2F + ((nt * 16 + kt) << 8) + lane * 8);
                    uint32_t bw[2] = {wv.x, wv.y};
                    #pragma unroll
                    for (int mtl = 0; mtl < 2; mtl++) mma_tf32(d[mtl][ntl], a[mtl], bw);
                }
            }
            #pragma unroll
            for (int mtl = 0; mtl < 2; mtl++) {
                int mt = wm * 2 + mtl;
                int rlo = (lane >> 2);
                #pragma unroll
                for (int ntl = 0; ntl < 4; ntl++) {
                    int kt = wn * 4 + ntl;
                    int c0 = (lane & 3) * 2;
                    const char* fb = smem + H2F + (mt * 16 + kt) * AFS;
                    #pragma unroll
                    for (int q = 0; q < 4; q++) {
                        int row8  = (q >> 1);
                        int col   = c0 + (q & 1);
                        int slot  = row8 | (((col >> 2) & 1) << 1);
                        int lane2 = ((rlo & 7) << 2) | (col & 3);
                        float v = fmaxf(d[mtl][ntl][q], 0.0f);
                        *(uint32_t*)(fb + slot * 128 + lane2 * 4) = f2tf32(v);
                    }
                }
            }
        }
        __syncthreads();

        // ---- Layer 3: U[64x64] = h2 @ W3 + b3, K=128, store to gmem ----
        {
            float d[2][2][4];
            #pragma unroll
            for (int mtl = 0; mtl < 2; mtl++)
                #pragma unroll
                for (int ntl = 0; ntl < 2; ntl++) {
                    int e = wn * 16 + ntl * 8 + (lane & 3) * 2;
                    float2 bb = *(const float2*)(smem + B3S + e * 4);
                    d[mtl][ntl][0] = bb.x; d[mtl][ntl][1] = bb.y;
                    d[mtl][ntl][2] = bb.x; d[mtl][ntl][3] = bb.y;
                }
            #pragma unroll 8
            for (int kt = 0; kt < 16; kt++) {
                uint32_t a[2][4];
                #pragma unroll
                for (int mtl = 0; mtl < 2; mtl++) {
                    const char* base = smem + H2F + ((wm * 2 + mtl) * 16 + kt) * AFS + lane * 4;
                    a[mtl][0] = *(const uint32_t*)(base);
                    a[mtl][1] = *(const uint32_t*)(base + 128);
                    a[mtl][2] = *(const uint32_t*)(base + 256);
                    a[mtl][3] = *(const uint32_t*)(base + 384);
                }
                #pragma unroll
                for (int ntl = 0; ntl < 2; ntl++) {
                    int nt = wn * 2 + ntl;
                    uint2 wv = *(const uint2*)(smem + W3F + ((nt * 16 + kt) << 8) + lane * 8);
                    uint32_t bw[2] = {wv.x, wv.y};
                    #pragma unroll
                    for (int mtl = 0; mtl < 2; mtl++) mma_tf32(d[mtl][ntl], a[mtl], bw);
                }
            }
            float* Ub = U_scratch + ((size_t)bk * C_ + j0) * E_;
            #pragma unroll
            for (int mtl = 0; mtl < 2; mtl++) {
                int r0 = wm * 32 + mtl * 16 + (lane >> 2);
                #pragma unroll
                for (int ntl = 0; ntl < 2; ntl++) {
                    int e = wn * 16 + ntl * 8 + (lane & 3) * 2;
                    float2 vA = make_float2(d[mtl][ntl][0], d[mtl][ntl][1]);
                    float2 vB = make_float2(d[mtl][ntl][2], d[mtl][ntl][3]);
                    *(float2*)&Ub[(size_t)r0 * E_ + e]       = vA;
                    *(float2*)&Ub[(size_t)(r0 + 8) * E_ + e] = vB;
                }
            }
        }
        __syncthreads();   // frag buffers safe to restage
    }
}

// ---------------------------------------------------------------------------
// Kernel 3: mma.sync tf32 attention (unchanged from R4 passing version)
// ---------------------------------------------------------------------------
#define AT_A 0
#define AT_B (64 * 1024)
#define AT_SMEM (128 * 1024)

__global__ void __launch_bounds__(256, 1)
attn_mma_kernel(const float* __restrict__ rc, const float* __restrict__ rq,
                const float* __restrict__ attc, const float* __restrict__ attq,
                float* __restrict__ out) {
    extern __shared__ char smem[];
    const int t = threadIdx.x;
    const int x = blockIdx.x;
    const int kg  = x & 15;
    const int Mq  = (x >> 4) & 3;
    const int map = (x >> 6) & 1;
    const int b   = x >> 7;

    const int wid  = t >> 5;
    const int lane = t & 31;
    const int wm = wid >> 2;
    const int wn = wid & 3;

    {
        const float* att = (map ? attq : attc) + (size_t)b * C_ * C_ + (size_t)(Mq * 64) * C_;
        #pragma unroll 4
        for (int it = 0; it < 16; it++) {
            int idx = it * 256 + t;
            int i  = idx >> 6;
            int j0 = (idx & 63) * 4;
            float4 v = *(const float4*)&att[(size_t)i * C_ + j0];
            uint4 p;
            p.x = f2tf32(v.x); p.y = f2tf32(v.y); p.z = f2tf32(v.z); p.w = f2tf32(v.w);
            int mt = i >> 4, kt = j0 >> 3;
            int sl = ((i >> 3) & 1) | (((j0 >> 2) & 1) << 1);
            uint32_t off = (uint32_t)(((mt * 32 + kt) * 4 + sl) * 128 + (i & 7) * 16);
            *(uint4*)(smem + AT_A + off) = p;
        }
    }

    float* outbase = out + (map ? (size_t)B_ * C_ * C_ * E_ : 0);
    const float* residbase = map ? rq : rc;

    float4 pre[16];
    int k0 = kg * 16;
    {
        const float* Ub = U_scratch + ((size_t)(b * C_ + k0)) * C_ * E_;
        #pragma unroll
        for (int it = 0; it < 16; it++) {
            int idx = it * 256 + t;
            int j = idx >> 4, e0 = (idx & 15) * 4;
            pre[it] = *(const float4*)&Ub[(size_t)j * E_ + e0];
        }
        #pragma unroll
        for (int it = 0; it < 16; it++) {
            int idx = it * 256 + t;
            int j = idx >> 4, e0 = (idx & 15) * 4;
            int kt = j >> 3, s2 = (j >> 2) & 1;
            float vv[4] = {pre[it].x, pre[it].y, pre[it].z, pre[it].w};
            #pragma unroll
            for (int r = 0; r < 4; r++) {
                int e = e0 + r;
                int nt = e >> 3;
                int ln = ((e & 7) << 2) | (j & 3);
                int Fp = (nt * 32 + ln) ^ (nt << 2);
                *(float*)(smem + AT_B + ((kt * 2 + s2) << 10) + Fp * 4) = vv[r];
            }
        }
    }
    __syncthreads();

    #pragma unroll 1
    for (int kk = 0; kk < 16; kk++) {
        const int k = k0 + kk;

        if (kk < 15) {
            const float* Ub = U_scratch + ((size_t)(b * C_ + k + 1)) * C_ * E_;
            #pragma unroll
            for (int it = 0; it < 16; it++) {
                int idx = it * 256 + t;
                int j = idx >> 4, e0 = (idx & 15) * 4;
                pre[it] = *(const float4*)&Ub[(size_t)j * E_ + e0];
            }
        }

        float d[2][2][4];
        #pragma unroll
        for (int i0 = 0; i0 < 2; i0++)
            #pragma unroll
            for (int i1 = 0; i1 < 2; i1++)
                #pragma unroll
                for (int i2 = 0; i2 < 4; i2++) d[i0][i1][i2] = 0.0f;

        #pragma unroll 4
        for (int kt = 0; kt < 32; kt++) {
            uint32_t a[2][4];
            #pragma unroll
            for (int mtl = 0; mtl < 2; mtl++) {
                int mt = wm * 2 + mtl;
                const char* base = smem + AT_A + ((mt * 32 + kt) * 4) * 128 + lane * 4;
                a[mtl][0] = *(const uint32_t*)(base);
                a[mtl][1] = *(const uint32_t*)(base + 128);
                a[mtl][2] = *(const uint32_t*)(base + 256);
                a[mtl][3] = *(const uint32_t*)(base + 384);
            }
            uint32_t bf[2][2];
            #pragma unroll
            for (int ntl = 0; ntl < 2; ntl++) {
                int nt = wn * 2 + ntl;
                int Fp = ((nt * 32 + lane) ^ (nt << 2)) * 4;
                float b0 = *(const float*)(smem + AT_B + ((kt * 2 + 0) << 10) + Fp);
                float b1 = *(const float*)(smem + AT_B + ((kt * 2 + 1) << 10) + Fp);
                bf[ntl][0] = f2tf32(b0);
                bf[ntl][1] = f2tf32(b1);
            }
            #pragma unroll
            for (int mtl = 0; mtl < 2; mtl++)
                #pragma unroll
                for (int ntl = 0; ntl < 2; ntl++)
                    mma_tf32(d[mtl][ntl], a[mtl], bf[ntl]);
        }
        __syncthreads();

        if (kk < 15) {
            #pragma unroll
            for (int it = 0; it < 16; it++) {
                int idx = it * 256 + t;
                int j = idx >> 4, e0 = (idx & 15) * 4;
                int kt = j >> 3, s2 = (j >> 2) & 1;
                float vv[4] = {pre[it].x, pre[it].y, pre[it].z, pre[it].w};
                #pragma unroll
                for (int r = 0; r < 4; r++) {
                    int e = e0 + r;
                    int nt = e >> 3;
                    int ln = ((e & 7) << 2) | (j & 3);
                    int Fp = (nt * 32 + ln) ^ (nt << 2);
                    *(float*)(smem + AT_B + ((kt * 2 + s2) << 10) + Fp * 4) = vv[r];
                }
            }
        }

        {
            const float* resid = residbase + ((size_t)(b * C_ + k) * C_) * E_;
            float* o = outbase + ((size_t)(b * C_ + k) * C_) * E_;
            #pragma unroll
            for (int mtl = 0; mtl < 2; mtl++) {
                int row = Mq * 64 + wm * 32 + mtl * 16 + (lane >> 2);
                #pragma unroll
                for (int ntl = 0; ntl < 2; ntl++) {
                    int e = wn * 16 + ntl * 8 + (lane & 3) * 2;
                    float2 rA = *(const float2*)&resid[(size_t)row * E_ + e];
                    float2 rB = *(const float2*)&resid[(size_t)(row + 8) * E_ + e];
                    float2 oA, oB;
                    oA.x = rA.x - ALPHA * d[mtl][ntl][0];
                    oA.y = rA.y - ALPHA * d[mtl][ntl][1];
                    oB.x = rB.x - ALPHA * d[mtl][ntl][2];
                    oB.y = rB.y - ALPHA * d[mtl][ntl][3];
                    *(float2*)&o[(size_t)row * E_ + e]       = oA;
                    *(float2*)&o[(size_t)(row + 8) * E_ + e] = oB;
                }
            }
        }

        if (kk < 15) __syncthreads();
    }
}

// ---------------------------------------------------------------------------
// Launch
// ---------------------------------------------------------------------------
extern "C" void kernel_launch(void* const* d_in, const int* in_sizes, int n_in,
                              void* d_out, int out_size) {
    const float* x    = (const float*)d_in[0];
    const float* y    = (const float*)d_in[1];
    const float* rc   = (const float*)d_in[2];
    const float* rq   = (const float*)d_in[3];
    const float* attc = (const float*)d_in[4];
    const float* attq = (const float*)d_in[5];
    const float* W1   = (const float*)d_in[6];
    const float* b1   = (const float*)d_in[7];
    const float* W2   = (const float*)d_in[8];
    const float* b2   = (const float*)d_in[9];
    const float* W3   = (const float*)d_in[10];
    const float* b3   = (const float*)d_in[11];
    float* out = (float*)d_out;

    cudaFuncSetAttribute(mlp_tc_kernel,   cudaFuncAttributeMaxDynamicSharedMemorySize, MLP_SMEM_B);
    cudaFuncSetAttribute(attn_mma_kernel, cudaFuncAttributeMaxDynamicSharedMemorySize, AT_SMEM);

    p_kernel<<<B_ * C_, H_>>>(x, y, W1, b1);
    mlp_tc_kernel<<<148, 256, MLP_SMEM_B>>>(rc, W1, b2, W2, W3, b3);
    attn_mma_kernel<<<512, 256, AT_SMEM>>>(rc, rq, attc, attq, out);
}

// round 7
// speedup vs baseline: 3.0781x; 1.1369x over previous
#include <cuda_runtime.h>
#include <cstdint>

#define B_ 4
#define C_ 256
#define Q_ 256
#define XD_ 64
#define YD_ 32
#define E_ 64
#define H_ 128
#define ALPHA 0.1f

#define NTILES (B_ * C_ * 4)

typedef unsigned long long u64;

// Scratch (static device globals — no runtime allocation)
// U stored in tf32 B-fragment layout per (b,k): 64KB blocks.
//   u32 offset(j,e) = (j>>3)*512 + (e>>3)*64 + ((((e&7)<<2)|(j&3))<<1) + ((j>>2)&1)
__device__ uint32_t U_scratch[(size_t)B_ * C_ * C_ * E_];
__device__ float    P_scratch[(size_t)B_ * C_ * H_];

// ---------------- mma.sync tf32 helpers (compute_80 features only) ----------
__device__ __forceinline__ uint32_t f2tf32(float f) {
    uint32_t r;
    asm("cvt.rna.tf32.f32 %0, %1;" : "=r"(r) : "f"(f));
    return r;
}
__device__ __forceinline__ void mma_tf32(float d[4], const uint32_t a[4], const uint32_t b[2]) {
    asm volatile(
        "mma.sync.aligned.m16n8k8.row.col.f32.tf32.tf32.f32 "
        "{%0,%1,%2,%3}, {%4,%5,%6,%7}, {%8,%9}, {%0,%1,%2,%3};"
        : "+f"(d[0]), "+f"(d[1]), "+f"(d[2]), "+f"(d[3])
        : "r"(a[0]), "r"(a[1]), "r"(a[2]), "r"(a[3]), "r"(b[0]), "r"(b[1]));
}
__device__ __forceinline__ uint32_t smem_u32(const void* p) {
    uint32_t a;
    asm("{ .reg .u64 t; cvta.to.shared.u64 t, %1; cvt.u32.u64 %0, t; }" : "=r"(a) : "l"(p));
    return a;
}
__device__ __forceinline__ void cp_async16(uint32_t s, const void* g) {
    asm volatile("cp.async.cg.shared.global [%0], [%1], 16;" :: "r"(s), "l"(g));
}
__device__ __forceinline__ void cp_commit() { asm volatile("cp.async.commit_group;" ::: "memory"); }
__device__ __forceinline__ void cp_wait0()  { asm volatile("cp.async.wait_group 0;" ::: "memory"); }

// ---------------------------------------------------------------------------
// Kernel 1: P[b,j,h] = b1[h] + x[b,j,:]·W1[0:64,h] + y[b,j,:]·W1[64:96,h]
// ---------------------------------------------------------------------------
__global__ void p_kernel(const float* __restrict__ x, const float* __restrict__ y,
                         const float* __restrict__ W1, const float* __restrict__ b1) {
    int bj = blockIdx.x;
    int h  = threadIdx.x;
    const float* xr = x + (size_t)bj * XD_;
    const float* yr = y + (size_t)bj * YD_;
    float acc = b1[h];
    #pragma unroll 8
    for (int d = 0; d < XD_; d++) acc = fmaf(xr[d], W1[d * H_ + h], acc);
    #pragma unroll 8
    for (int d = 0; d < YD_; d++) acc = fmaf(yr[d], W1[(XD_ + d) * H_ + h], acc);
    P_scratch[(size_t)bj * H_ + h] = acc;
}

// ---------------------------------------------------------------------------
// Kernel 2: persistent tensor-core MLP (mma.sync tf32).
//   Layer-3 epilogue stores U in the global B-fragment tf32 layout.
// ---------------------------------------------------------------------------
#define W1F   0
#define W2F   32768
#define W3F   98304
#define B2S   131072
#define B3S   131584
#define AFS   516
#define INF   131840
#define H1F   148352
#define H2F   181376
#define MLP_SMEM_B 214400

__global__ void __launch_bounds__(256, 1)
mlp_tc_kernel(const float* __restrict__ rc,
              const float* __restrict__ W1,
              const float* __restrict__ b2v,
              const float* __restrict__ W2,
              const float* __restrict__ W3,
              const float* __restrict__ b3v) {
    extern __shared__ char smem[];
    const int t    = threadIdx.x;
    const int wid  = t >> 5;
    const int lane = t & 31;
    const int wm   = wid >> 2;     // 0..1
    const int wn   = wid & 3;      // 0..3

    // ---- Stage weights fragment-major (once) ----
    for (int i = t; i < 64 * 128; i += 256) {
        int k = i >> 7, n = i & 127;
        uint32_t v = f2tf32(W1[(96 + k) * H_ + n]);
        int fr = (n >> 3) * 8 + (k >> 3);
        uint32_t off = W1F + (fr << 8) + ((((n & 7) << 2) | (k & 3)) << 3) + (((k & 7) >> 2) << 2);
        *(uint32_t*)(smem + off) = v;
    }
    for (int i = t; i < 128 * 128; i += 256) {
        int k = i >> 7, n = i & 127;
        uint32_t v = f2tf32(W2[(size_t)k * H_ + n]);
        int fr = (n >> 3) * 16 + (k >> 3);
        uint32_t off = W2F + (fr << 8) + ((((n & 7) << 2) | (k & 3)) << 3) + (((k & 7) >> 2) << 2);
        *(uint32_t*)(smem + off) = v;
    }
    for (int i = t; i < 128 * 64; i += 256) {
        int k = i >> 6, n = i & 63;
        uint32_t v = f2tf32(W3[(size_t)k * E_ + n]);
        int fr = (n >> 3) * 16 + (k >> 3);
        uint32_t off = W3F + (fr << 8) + ((((n & 7) << 2) | (k & 3)) << 3) + (((k & 7) >> 2) << 2);
        *(uint32_t*)(smem + off) = v;
    }
    if (t < 128) *(float*)(smem + B2S + t * 4) = b2v[t];
    if (t < 64)  *(float*)(smem + B3S + t * 4) = b3v[t];
    __syncthreads();

    for (int tile = blockIdx.x; tile < NTILES; tile += gridDim.x) {
        const int jsub = tile & 3;
        const int bk   = tile >> 2;
        const int b    = bk >> 8;
        const int j0   = jsub * 64;

        // ---- Stage input rc tile as A-fragments (tf32) ----
        {
            const float* rcin = rc + ((size_t)bk * C_ + j0) * E_;
            #pragma unroll
            for (int it = 0; it < 4; it++) {
                int idx = it * 256 + t;
                int r = idx >> 4, e4 = idx & 15;
                float4 v = *(const float4*)&rcin[(size_t)r * E_ + e4 * 4];
                float vv[4] = {v.x, v.y, v.z, v.w};
                #pragma unroll
                for (int c = 0; c < 4; c++) {
                    int e = e4 * 4 + c;
                    int mt = r >> 4, kt = e >> 3;
                    int slot  = ((r >> 3) & 1) | (((e >> 2) & 1) << 1);
                    int lane2 = ((r & 7) << 2) | (e & 3);
                    uint32_t off = INF + (mt * 8 + kt) * AFS + slot * 128 + lane2 * 4;
                    *(uint32_t*)(smem + off) = f2tf32(vv[c]);
                }
            }
        }
        __syncthreads();

        // ---- Layer 1: h1[64x128] = relu(P + in @ W1e), K=64 ----
        {
            float d[2][4][4];
            const float* Pp = P_scratch + (size_t)(b * C_ + j0) * H_;
            #pragma unroll
            for (int mtl = 0; mtl < 2; mtl++) {
                int r0 = wm * 32 + mtl * 16 + (lane >> 2);
                #pragma unroll
                for (int ntl = 0; ntl < 4; ntl++) {
                    int col = wn * 32 + ntl * 8 + (lane & 3) * 2;
                    float2 p0 = *(const float2*)&Pp[(size_t)r0 * H_ + col];
                    float2 p1 = *(const float2*)&Pp[(size_t)(r0 + 8) * H_ + col];
                    d[mtl][ntl][0] = p0.x; d[mtl][ntl][1] = p0.y;
                    d[mtl][ntl][2] = p1.x; d[mtl][ntl][3] = p1.y;
                }
            }
            #pragma unroll
            for (int kt = 0; kt < 8; kt++) {
                uint32_t a[2][4];
                #pragma unroll
                for (int mtl = 0; mtl < 2; mtl++) {
                    const char* base = smem + INF + ((wm * 2 + mtl) * 8 + kt) * AFS + lane * 4;
                    a[mtl][0] = *(const uint32_t*)(base);
                    a[mtl][1] = *(const uint32_t*)(base + 128);
                    a[mtl][2] = *(const uint32_t*)(base + 256);
                    a[mtl][3] = *(const uint32_t*)(base + 384);
                }
                #pragma unroll
                for (int ntl = 0; ntl < 4; ntl++) {
                    int nt = wn * 4 + ntl;
                    uint2 wv = *(const uint2*)(smem + W1F + ((nt * 8 + kt) << 8) + lane * 8);
                    uint32_t bw[2] = {wv.x, wv.y};
                    #pragma unroll
                    for (int mtl = 0; mtl < 2; mtl++) mma_tf32(d[mtl][ntl], a[mtl], bw);
                }
            }
            #pragma unroll
            for (int mtl = 0; mtl < 2; mtl++) {
                int mt = wm * 2 + mtl;
                int rlo = (lane >> 2);
                #pragma unroll
                for (int ntl = 0; ntl < 4; ntl++) {
                    int kt = wn * 4 + ntl;
                    int c0 = (lane & 3) * 2;
                    const char* fb = smem + H1F + (mt * 16 + kt) * AFS;
                    #pragma unroll
                    for (int q = 0; q < 4; q++) {
                        int row8  = (q >> 1);
                        int col   = c0 + (q & 1);
                        int slot  = row8 | (((col >> 2) & 1) << 1);
                        int lane2 = ((rlo & 7) << 2) | (col & 3);
                        float v = fmaxf(d[mtl][ntl][q], 0.0f);
                        *(uint32_t*)(fb + slot * 128 + lane2 * 4) = f2tf32(v);
                    }
                }
            }
        }
        __syncthreads();

        // ---- Layer 2: h2[64x128] = relu(h1 @ W2 + b2), K=128 ----
        {
            float d[2][4][4];
            #pragma unroll
            for (int mtl = 0; mtl < 2; mtl++)
                #pragma unroll
                for (int ntl = 0; ntl < 4; ntl++) {
                    int col = wn * 32 + ntl * 8 + (lane & 3) * 2;
                    float2 bb = *(const float2*)(smem + B2S + col * 4);
                    d[mtl][ntl][0] = bb.x; d[mtl][ntl][1] = bb.y;
                    d[mtl][ntl][2] = bb.x; d[mtl][ntl][3] = bb.y;
                }
            #pragma unroll 8
            for (int kt = 0; kt < 16; kt++) {
                uint32_t a[2][4];
                #pragma unroll
                for (int mtl = 0; mtl < 2; mtl++) {
                    const char* base = smem + H1F + ((wm * 2 + mtl) * 16 + kt) * AFS + lane * 4;
                    a[mtl][0] = *(const uint32_t*)(base);
                    a[mtl][1] = *(const uint32_t*)(base + 128);
                    a[mtl][2] = *(const uint32_t*)(base + 256);
                    a[mtl][3] = *(const uint32_t*)(base + 384);
                }
                #pragma unroll
                for (int ntl = 0; ntl < 4; ntl++) {
                    int nt = wn * 4 + ntl;
                    uint2 wv = *(const uint2*)(smem + W2F + ((nt * 16 + kt) << 8) + lane * 8);
                    uint32_t bw[2] = {wv.x, wv.y};
                    #pragma unroll
                    for (int mtl = 0; mtl < 2; mtl++) mma_tf32(d[mtl][ntl], a[mtl], bw);
                }
            }
            #pragma unroll
            for (int mtl = 0; mtl < 2; mtl++) {
                int mt = wm * 2 + mtl;
                int rlo = (lane >> 2);
                #pragma unroll
                for (int ntl = 0; ntl < 4; ntl++) {
                    int kt = wn * 4 + ntl;
                    int c0 = (lane & 3) * 2;
                    const char* fb = smem + H2F + (mt * 16 + kt) * AFS;
                    #pragma unroll
                    for (int q = 0; q < 4; q++) {
                        int row8  = (q >> 1);
                        int col   = c0 + (q & 1);
                        int slot  = row8 | (((col >> 2) & 1) << 1);
                        int lane2 = ((rlo & 7) << 2) | (col & 3);
                        float v = fmaxf(d[mtl][ntl][q], 0.0f);
                        *(uint32_t*)(fb + slot * 128 + lane2 * 4) = f2tf32(v);
                    }
                }
            }
        }
        __syncthreads();

        // ---- Layer 3: U[64x64] = h2 @ W3 + b3, K=128 -> frag-layout gmem ----
        {
            float d[2][2][4];
            #pragma unroll
            for (int mtl = 0; mtl < 2; mtl++)
                #pragma unroll
                for (int ntl = 0; ntl < 2; ntl++) {
                    int e = wn * 16 + ntl * 8 + (lane & 3) * 2;
                    float2 bb = *(const float2*)(smem + B3S + e * 4);
                    d[mtl][ntl][0] = bb.x; d[mtl][ntl][1] = bb.y;
                    d[mtl][ntl][2] = bb.x; d[mtl][ntl][3] = bb.y;
                }
            #pragma unroll 8
            for (int kt = 0; kt < 16; kt++) {
                uint32_t a[2][4];
                #pragma unroll
                for (int mtl = 0; mtl < 2; mtl++) {
                    const char* base = smem + H2F + ((wm * 2 + mtl) * 16 + kt) * AFS + lane * 4;
                    a[mtl][0] = *(const uint32_t*)(base);
                    a[mtl][1] = *(const uint32_t*)(base + 128);
                    a[mtl][2] = *(const uint32_t*)(base + 256);
                    a[mtl][3] = *(const uint32_t*)(base + 384);
                }
                #pragma unroll
                for (int ntl = 0; ntl < 2; ntl++) {
                    int nt = wn * 2 + ntl;
                    uint2 wv = *(const uint2*)(smem + W3F + ((nt * 16 + kt) << 8) + lane * 8);
                    uint32_t bw[2] = {wv.x, wv.y};
                    #pragma unroll
                    for (int mtl = 0; mtl < 2; mtl++) mma_tf32(d[mtl][ntl], a[mtl], bw);
                }
            }
            // Store as tf32 in global B-fragment layout (16K u32 per bk).
            // u32 off = (j>>3)*512 + (e>>3)*64 + ((((e&7)<<2)|(j&3))<<1) + ((j>>2)&1)
            uint32_t* Ub = U_scratch + (size_t)bk * 16384;
            #pragma unroll
            for (int mtl = 0; mtl < 2; mtl++) {
                #pragma unroll
                for (int ntl = 0; ntl < 2; ntl++) {
                    #pragma unroll
                    for (int q = 0; q < 4; q++) {
                        int r = wm * 32 + mtl * 16 + (lane >> 2) + (q >> 1) * 8;
                        int j = j0 + r;
                        int e = wn * 16 + ntl * 8 + (lane & 3) * 2 + (q & 1);
                        uint32_t off = (uint32_t)((j >> 3) * 512
                                      + ((e >> 3) << 6)
                                      + (((((e & 7) << 2) | (j & 3))) << 1)
                                      + ((j >> 2) & 1));
                        Ub[off] = f2tf32(d[mtl][ntl][q]);
                    }
                }
            }
        }
        __syncthreads();
    }
}

// ---------------------------------------------------------------------------
// Kernel 3: mma.sync tf32 attention.
//   B (U frags) memcpy'd via cp.async into a double buffer; no scatter,
//   no cvt. A staged once per CTA (tf32 frag-major).
// ---------------------------------------------------------------------------
#define AT_A  0
#define AT_B0 65536
#define AT_B1 131072
#define AT_SMEM 196608

__global__ void __launch_bounds__(256, 1)
attn_mma_kernel(const float* __restrict__ rc, const float* __restrict__ rq,
                const float* __restrict__ attc, const float* __restrict__ attq,
                float* __restrict__ out) {
    extern __shared__ char smem[];
    const uint32_t smem_base = smem_u32(smem);
    const int t = threadIdx.x;
    const int x = blockIdx.x;
    const int kg  = x & 15;
    const int Mq  = (x >> 4) & 3;
    const int map = (x >> 6) & 1;
    const int b   = x >> 7;

    const int wid  = t >> 5;
    const int lane = t & 31;
    const int wm = wid >> 2;
    const int wn = wid & 3;

    const int k0 = kg * 16;

    // ---- Kick off B stage for k0 into buf0 (async) ----
    {
        const char* src = (const char*)(U_scratch + ((size_t)(b * C_ + k0)) * 16384);
        #pragma unroll
        for (int it = 0; it < 16; it++) {
            int o = (it * 256 + t) * 16;
            cp_async16(smem_base + AT_B0 + o, src + o);
        }
        cp_commit();
    }

    // ---- Stage A once: att rows [Mq*64, Mq*64+64), tf32 frag-major ----
    {
        const float* att = (map ? attq : attc) + (size_t)b * C_ * C_ + (size_t)(Mq * 64) * C_;
        #pragma unroll 4
        for (int it = 0; it < 16; it++) {
            int idx = it * 256 + t;
            int i  = idx >> 6;
            int j0 = (idx & 63) * 4;
            float4 v = *(const float4*)&att[(size_t)i * C_ + j0];
            uint4 p;
            p.x = f2tf32(v.x); p.y = f2tf32(v.y); p.z = f2tf32(v.z); p.w = f2tf32(v.w);
            int mt = i >> 4, kt = j0 >> 3;
            int sl = ((i >> 3) & 1) | (((j0 >> 2) & 1) << 1);
            uint32_t off = (uint32_t)(((mt * 32 + kt) * 4 + sl) * 128 + (i & 7) * 16);
            *(uint4*)(smem + AT_A + off) = p;
        }
    }
    cp_wait0();
    __syncthreads();

    float* outbase = out + (map ? (size_t)B_ * C_ * C_ * E_ : 0);
    const float* residbase = map ? rq : rc;

    uint32_t bufoff = AT_B0;
    #pragma unroll 1
    for (int kk = 0; kk < 16; kk++) {
        const int k = k0 + kk;

        // async-stage next k's B into the other buffer (overlaps mma)
        if (kk < 15) {
            const char* src = (const char*)(U_scratch + ((size_t)(b * C_ + k + 1)) * 16384);
            uint32_t dst = smem_base + (bufoff ^ (AT_B0 ^ AT_B1));
            #pragma unroll
            for (int it = 0; it < 16; it++) {
                int o = (it * 256 + t) * 16;
                cp_async16(dst + o, src + o);
            }
            cp_commit();
        }

        // ---- mma mainloop: D[64x64] += A[64x256] * B[256x64] ----
        float d[2][2][4];
        #pragma unroll
        for (int i0 = 0; i0 < 2; i0++)
            #pragma unroll
            for (int i1 = 0; i1 < 2; i1++)
                #pragma unroll
                for (int i2 = 0; i2 < 4; i2++) d[i0][i1][i2] = 0.0f;

        #pragma unroll 4
        for (int kt = 0; kt < 32; kt++) {
            uint32_t a[2][4];
            #pragma unroll
            for (int mtl = 0; mtl < 2; mtl++) {
                int mt = wm * 2 + mtl;
                const char* base = smem + AT_A + ((mt * 32 + kt) * 4) * 128 + lane * 4;
                a[mtl][0] = *(const uint32_t*)(base);
                a[mtl][1] = *(const uint32_t*)(base + 128);
                a[mtl][2] = *(const uint32_t*)(base + 256);
                a[mtl][3] = *(const uint32_t*)(base + 384);
            }
            uint32_t bw[2][2];
            #pragma unroll
            for (int ntl = 0; ntl < 2; ntl++) {
                int nt = wn * 2 + ntl;
                uint2 bv = *(const uint2*)(smem + bufoff + kt * 2048 + (nt * 32 + lane) * 8);
                bw[ntl][0] = bv.x; bw[ntl][1] = bv.y;
            }
            #pragma unroll
            for (int mtl = 0; mtl < 2; mtl++)
                #pragma unroll
                for (int ntl = 0; ntl < 2; ntl++)
                    mma_tf32(d[mtl][ntl], a[mtl], bw[ntl]);
        }

        // ---- epilogue: out = resid - ALPHA * D ----
        {
            const float* resid = residbase + ((size_t)(b * C_ + k) * C_) * E_;
            float* o = outbase + ((size_t)(b * C_ + k) * C_) * E_;
            #pragma unroll
            for (int mtl = 0; mtl < 2; mtl++) {
                int row = Mq * 64 + wm * 32 + mtl * 16 + (lane >> 2);
                #pragma unroll
                for (int ntl = 0; ntl < 2; ntl++) {
                    int e = wn * 16 + ntl * 8 + (lane & 3) * 2;
                    float2 rA = *(const float2*)&resid[(size_t)row * E_ + e];
                    float2 rB = *(const float2*)&resid[(size_t)(row + 8) * E_ + e];
                    float2 oA, oB;
                    oA.x = rA.x - ALPHA * d[mtl][ntl][0];
                    oA.y = rA.y - ALPHA * d[mtl][ntl][1];
                    oB.x = rB.x - ALPHA * d[mtl][ntl][2];
                    oB.y = rB.y - ALPHA * d[mtl][ntl][3];
                    *(float2*)&o[(size_t)row * E_ + e]       = oA;
                    *(float2*)&o[(size_t)(row + 8) * E_ + e] = oB;
                }
            }
        }

        if (kk < 15) {
            cp_wait0();
            __syncthreads();
            bufoff ^= (AT_B0 ^ AT_B1);
        }
    }
}

// ---------------------------------------------------------------------------
// Launch
// ---------------------------------------------------------------------------
extern "C" void kernel_launch(void* const* d_in, const int* in_sizes, int n_in,
                              void* d_out, int out_size) {
    const float* x    = (const float*)d_in[0];
    const float* y    = (const float*)d_in[1];
    const float* rc   = (const float*)d_in[2];
    const float* rq   = (const float*)d_in[3];
    const float* attc = (const float*)d_in[4];
    const float* attq = (const float*)d_in[5];
    const float* W1   = (const float*)d_in[6];
    const float* b1   = (const float*)d_in[7];
    const float* W2   = (const float*)d_in[8];
    const float* b2   = (const float*)d_in[9];
    const float* W3   = (const float*)d_in[10];
    const float* b3   = (const float*)d_in[11];
    float* out = (float*)d_out;

    cudaFuncSetAttribute(mlp_tc_kernel,   cudaFuncAttributeMaxDynamicSharedMemorySize, MLP_SMEM_B);
    cudaFuncSetAttribute(attn_mma_kernel, cudaFuncAttributeMaxDynamicSharedMemorySize, AT_SMEM);

    p_kernel<<<B_ * C_, H_>>>(x, y, W1, b1);
    mlp_tc_kernel<<<148, 256, MLP_SMEM_B>>>(rc, W1, b2, W2, W3, b3);
    attn_mma_kernel<<<512, 256, AT_SMEM>>>(rc, rq, attc, attq, out);
}

// round 8
// speedup vs baseline: 5.0937x; 1.6548x over previous
#include <cuda_runtime.h>
#include <cstdint>

#define B_ 4
#define C_ 256
#define Q_ 256
#define XD_ 64
#define YD_ 32
#define E_ 64
#define H_ 128
#define ALPHA 0.1f

#define NTILES (B_ * C_ * 4)

typedef unsigned long long u64;

// U stored in fp16 B-fragment (m16n8k16) layout per (b,k): 32KB blocks.
//   u32 word idx = ((ktg*8 + nt)*32 + lane)*2 + r
//   word(k= ktg*16 + (lane&3)*2 + r*8 (+1), n = nt*8 + (lane>>2))
__device__ uint32_t U_scratch[(size_t)B_ * C_ * C_ * E_ / 2];
__device__ float    P_scratch[(size_t)B_ * C_ * H_];

// ---------------- helpers (compute_80 features only) ----------
__device__ __forceinline__ uint32_t pack_h2(float lo, float hi) {
    uint32_t r;
    asm("cvt.rn.f16x2.f32 %0, %1, %2;" : "=r"(r) : "f"(hi), "f"(lo));
    return r;
}
__device__ __forceinline__ void mma_f16(float d[4], const uint32_t a[4], const uint32_t b[2]) {
    asm volatile(
        "mma.sync.aligned.m16n8k16.row.col.f32.f16.f16.f32 "
        "{%0,%1,%2,%3}, {%4,%5,%6,%7}, {%8,%9}, {%0,%1,%2,%3};"
        : "+f"(d[0]), "+f"(d[1]), "+f"(d[2]), "+f"(d[3])
        : "r"(a[0]), "r"(a[1]), "r"(a[2]), "r"(a[3]), "r"(b[0]), "r"(b[1]));
}
__device__ __forceinline__ uint32_t smem_u32(const void* p) {
    uint32_t a;
    asm("{ .reg .u64 t; cvta.to.shared.u64 t, %1; cvt.u32.u64 %0, t; }" : "=r"(a) : "l"(p));
    return a;
}
__device__ __forceinline__ void cp_async16(uint32_t s, const void* g) {
    asm volatile("cp.async.cg.shared.global [%0], [%1], 16;" :: "r"(s), "l"(g));
}
__device__ __forceinline__ void cp_commit() { asm volatile("cp.async.commit_group;" ::: "memory"); }
__device__ __forceinline__ void cp_wait0()  { asm volatile("cp.async.wait_group 0;" ::: "memory"); }

// A-fragment geometry (m16n8k16): per (mt,kt) tile: [reg 0..3][lane 0..31] u32
#define REGS 136           // reg stride bytes (8-aligned, bank-skewed)
#define TILES 544          // tile stride bytes (= 4*REGS)

// ---------------------------------------------------------------------------
// Kernel 1: P[b,j,h] (fp32)
// ---------------------------------------------------------------------------
__global__ void p_kernel(const float* __restrict__ x, const float* __restrict__ y,
                         const float* __restrict__ W1, const float* __restrict__ b1) {
    int bj = blockIdx.x;
    int h  = threadIdx.x;
    const float* xr = x + (size_t)bj * XD_;
    const float* yr = y + (size_t)bj * YD_;
    float acc = b1[h];
    #pragma unroll 8
    for (int d = 0; d < XD_; d++) acc = fmaf(xr[d], W1[d * H_ + h], acc);
    #pragma unroll 8
    for (int d = 0; d < YD_; d++) acc = fmaf(yr[d], W1[(XD_ + d) * H_ + h], acc);
    P_scratch[(size_t)bj * H_ + h] = acc;
}

// ---------------------------------------------------------------------------
// Kernel 2: persistent fp16 tensor-core MLP.
// smem layout (bytes):
//   W1F 0      : 16KB  (kt4  x nt16: u32 ((kt*16+nt)*32+lane)*2+r)
//   W2F 16384  : 32KB  (kt8  x nt16)
//   W3F 49152  : 16KB  (kt8  x nt8)
//   B2S 65536, B3S 66048
//   INF 66304  : 8704  (A-frags mt4 x kt4)     [also BOUNCE 9216B in L3 phase]
//   H1F 75008  : 17408 (A-frags mt4 x kt8)
//   H2F 92416  : 17408
// ---------------------------------------------------------------------------
#define W1F 0
#define W2F 16384
#define W3F 49152
#define B2S 65536
#define B3S 66048
#define INF 66304
#define H1F 75008
#define H2F 92416
#define BOUNCE 66304
#define ROWB 144
#define MLP_SMEM_B 109824

__global__ void __launch_bounds__(256, 2)
mlp_tc_kernel(const float* __restrict__ rc,
              const float* __restrict__ W1,
              const float* __restrict__ b2v,
              const float* __restrict__ W2,
              const float* __restrict__ W3,
              const float* __restrict__ b3v) {
    extern __shared__ char smem[];
    const int t    = threadIdx.x;
    const int wid  = t >> 5;
    const int lane = t & 31;
    const int wm   = wid >> 2;     // 0..1
    const int wn   = wid & 3;      // 0..3

    // ---- Stage weights as fp16 B-fragments (once) ----
    // W1 (rows 96..159 of W1 input): 4096 words
    for (int i = t; i < 4096; i += 256) {
        int r = i & 1, ln = (i >> 1) & 31, nt = (i >> 6) & 15, kt = i >> 10;
        int k = kt * 16 + (ln & 3) * 2 + r * 8;
        int n = nt * 8 + (ln >> 2);
        float v0 = W1[(96 + k) * H_ + n];
        float v1 = W1[(96 + k + 1) * H_ + n];
        *(uint32_t*)(smem + W1F + i * 4) = pack_h2(v0, v1);
    }
    // W2: 8192 words
    for (int i = t; i < 8192; i += 256) {
        int r = i & 1, ln = (i >> 1) & 31, nt = (i >> 6) & 15, kt = i >> 10;
        int k = kt * 16 + (ln & 3) * 2 + r * 8;
        int n = nt * 8 + (ln >> 2);
        *(uint32_t*)(smem + W2F + i * 4) = pack_h2(W2[(size_t)k * H_ + n], W2[(size_t)(k + 1) * H_ + n]);
    }
    // W3: 4096 words
    for (int i = t; i < 4096; i += 256) {
        int r = i & 1, ln = (i >> 1) & 31, nt = (i >> 6) & 7, kt = i >> 9;
        int k = kt * 16 + (ln & 3) * 2 + r * 8;
        int n = nt * 8 + (ln >> 2);
        *(uint32_t*)(smem + W3F + i * 4) = pack_h2(W3[(size_t)k * E_ + n], W3[(size_t)(k + 1) * E_ + n]);
    }
    if (t < 128) *(float*)(smem + B2S + t * 4) = b2v[t];
    if (t < 64)  *(float*)(smem + B3S + t * 4) = b3v[t];
    __syncthreads();

    for (int tile = blockIdx.x; tile < NTILES; tile += gridDim.x) {
        const int jsub = tile & 3;
        const int bk   = tile >> 2;
        const int b    = bk >> 8;
        const int j0   = jsub * 64;

        // ---- Stage input rc tile as fp16 A-fragments ----
        {
            const float* rcin = rc + ((size_t)bk * C_ + j0) * E_;
            #pragma unroll
            for (int it = 0; it < 4; it++) {
                int idx = it * 256 + t;            // float4 index
                int r  = idx >> 4;                 // row 0..63
                int e0 = (idx & 15) * 4;           // col 0..60
                float4 v = *(const float4*)&rcin[(size_t)r * E_ + e0];
                int mt = r >> 4, kt = e0 >> 4;
                int reg = ((r >> 3) & 1) | (((e0 >> 3) & 1) << 1);
                int lp  = (r & 7) * 4 + ((e0 & 7) >> 1);
                uint2 w;
                w.x = pack_h2(v.x, v.y);
                w.y = pack_h2(v.z, v.w);
                *(uint2*)(smem + INF + (mt * 4 + kt) * TILES + reg * REGS + lp * 4) = w;
            }
        }
        __syncthreads();

        // ---- Layer 1: h1[64x128] = relu(P + in @ W1e), K=64 (4 kt) ----
        {
            float d[2][4][4];
            const float* Pp = P_scratch + (size_t)(b * C_ + j0) * H_;
            #pragma unroll
            for (int mtl = 0; mtl < 2; mtl++) {
                int r0 = wm * 32 + mtl * 16 + (lane >> 2);
                #pragma unroll
                for (int ntl = 0; ntl < 4; ntl++) {
                    int col = wn * 32 + ntl * 8 + (lane & 3) * 2;
                    float2 p0 = *(const float2*)&Pp[(size_t)r0 * H_ + col];
                    float2 p1 = *(const float2*)&Pp[(size_t)(r0 + 8) * H_ + col];
                    d[mtl][ntl][0] = p0.x; d[mtl][ntl][1] = p0.y;
                    d[mtl][ntl][2] = p1.x; d[mtl][ntl][3] = p1.y;
                }
            }
            #pragma unroll
            for (int kt = 0; kt < 4; kt++) {
                uint32_t a[2][4];
                #pragma unroll
                for (int mtl = 0; mtl < 2; mtl++) {
                    const char* base = smem + INF + ((wm * 2 + mtl) * 4 + kt) * TILES + lane * 4;
                    a[mtl][0] = *(const uint32_t*)(base);
                    a[mtl][1] = *(const uint32_t*)(base + REGS);
                    a[mtl][2] = *(const uint32_t*)(base + 2 * REGS);
                    a[mtl][3] = *(const uint32_t*)(base + 3 * REGS);
                }
                #pragma unroll
                for (int ntl = 0; ntl < 4; ntl++) {
                    int nt = wn * 4 + ntl;
                    uint2 bv = *(const uint2*)(smem + W1F + ((kt * 16 + nt) * 32 + lane) * 8);
                    uint32_t bw[2] = {bv.x, bv.y};
                    #pragma unroll
                    for (int mtl = 0; mtl < 2; mtl++) mma_f16(d[mtl][ntl], a[mtl], bw);
                }
            }
            // relu + pack + store as A-frags for layer 2 (conflict-free perm)
            #pragma unroll
            for (int mtl = 0; mtl < 2; mtl++) {
                int mt2 = wm * 2 + mtl;
                int lp  = (lane >> 2) * 4 + (lane & 3);
                #pragma unroll
                for (int ntl = 0; ntl < 4; ntl++) {
                    int kt2 = wn * 2 + (ntl >> 1);
                    int rlo = (ntl & 1) * 2;
                    const char* fb = smem + H1F + (mt2 * 8 + kt2) * TILES + lp * 4;
                    *(uint32_t*)(fb + rlo * REGS) =
                        pack_h2(fmaxf(d[mtl][ntl][0], 0.0f), fmaxf(d[mtl][ntl][1], 0.0f));
                    *(uint32_t*)(fb + (rlo + 1) * REGS) =
                        pack_h2(fmaxf(d[mtl][ntl][2], 0.0f), fmaxf(d[mtl][ntl][3], 0.0f));
                }
            }
        }
        __syncthreads();

        // ---- Layer 2: h2[64x128] = relu(h1 @ W2 + b2), K=128 (8 kt) ----
        {
            float d[2][4][4];
            #pragma unroll
            for (int mtl = 0; mtl < 2; mtl++)
                #pragma unroll
                for (int ntl = 0; ntl < 4; ntl++) {
                    int col = wn * 32 + ntl * 8 + (lane & 3) * 2;
                    float2 bb = *(const float2*)(smem + B2S + col * 4);
                    d[mtl][ntl][0] = bb.x; d[mtl][ntl][1] = bb.y;
                    d[mtl][ntl][2] = bb.x; d[mtl][ntl][3] = bb.y;
                }
            #pragma unroll
            for (int kt = 0; kt < 8; kt++) {
                uint32_t a[2][4];
                #pragma unroll
                for (int mtl = 0; mtl < 2; mtl++) {
                    const char* base = smem + H1F + ((wm * 2 + mtl) * 8 + kt) * TILES + lane * 4;
                    a[mtl][0] = *(const uint32_t*)(base);
                    a[mtl][1] = *(const uint32_t*)(base + REGS);
                    a[mtl][2] = *(const uint32_t*)(base + 2 * REGS);
                    a[mtl][3] = *(const uint32_t*)(base + 3 * REGS);
                }
                #pragma unroll
                for (int ntl = 0; ntl < 4; ntl++) {
                    int nt = wn * 4 + ntl;
                    uint2 bv = *(const uint2*)(smem + W2F + ((kt * 16 + nt) * 32 + lane) * 8);
                    uint32_t bw[2] = {bv.x, bv.y};
                    #pragma unroll
                    for (int mtl = 0; mtl < 2; mtl++) mma_f16(d[mtl][ntl], a[mtl], bw);
                }
            }
            #pragma unroll
            for (int mtl = 0; mtl < 2; mtl++) {
                int mt2 = wm * 2 + mtl;
                int lp  = (lane >> 2) * 4 + (lane & 3);
                #pragma unroll
                for (int ntl = 0; ntl < 4; ntl++) {
                    int kt2 = wn * 2 + (ntl >> 1);
                    int rlo = (ntl & 1) * 2;
                    const char* fb = smem + H2F + (mt2 * 8 + kt2) * TILES + lp * 4;
                    *(uint32_t*)(fb + rlo * REGS) =
                        pack_h2(fmaxf(d[mtl][ntl][0], 0.0f), fmaxf(d[mtl][ntl][1], 0.0f));
                    *(uint32_t*)(fb + (rlo + 1) * REGS) =
                        pack_h2(fmaxf(d[mtl][ntl][2], 0.0f), fmaxf(d[mtl][ntl][3], 0.0f));
                }
            }
        }
        __syncthreads();

        // ---- Layer 3: U[64x64] = h2 @ W3 + b3, K=128 -> bounce (fp16) ----
        {
            float d[2][2][4];
            #pragma unroll
            for (int mtl = 0; mtl < 2; mtl++)
                #pragma unroll
                for (int ntl = 0; ntl < 2; ntl++) {
                    int e = wn * 16 + ntl * 8 + (lane & 3) * 2;
                    float2 bb = *(const float2*)(smem + B3S + e * 4);
                    d[mtl][ntl][0] = bb.x; d[mtl][ntl][1] = bb.y;
                    d[mtl][ntl][2] = bb.x; d[mtl][ntl][3] = bb.y;
                }
            #pragma unroll
            for (int kt = 0; kt < 8; kt++) {
                uint32_t a[2][4];
                #pragma unroll
                for (int mtl = 0; mtl < 2; mtl++) {
                    const char* base = smem + H2F + ((wm * 2 + mtl) * 8 + kt) * TILES + lane * 4;
                    a[mtl][0] = *(const uint32_t*)(base);
                    a[mtl][1] = *(const uint32_t*)(base + REGS);
                    a[mtl][2] = *(const uint32_t*)(base + 2 * REGS);
                    a[mtl][3] = *(const uint32_t*)(base + 3 * REGS);
                }
                #pragma unroll
                for (int ntl = 0; ntl < 2; ntl++) {
                    int nt = wn * 2 + ntl;
                    uint2 bv = *(const uint2*)(smem + W3F + ((kt * 8 + nt) * 32 + lane) * 8);
                    uint32_t bw[2] = {bv.x, bv.y};
                    #pragma unroll
                    for (int mtl = 0; mtl < 2; mtl++) mma_f16(d[mtl][ntl], a[mtl], bw);
                }
            }
            // write fp16 into bounce [64 x 64], row stride 144B (conflict-free)
            #pragma unroll
            for (int mtl = 0; mtl < 2; mtl++) {
                int row = wm * 32 + mtl * 16 + (lane >> 2);
                #pragma unroll
                for (int ntl = 0; ntl < 2; ntl++) {
                    int e = wn * 16 + ntl * 8 + (lane & 3) * 2;
                    *(uint32_t*)(smem + BOUNCE + row * ROWB + e * 2) =
                        pack_h2(d[mtl][ntl][0], d[mtl][ntl][1]);
                    *(uint32_t*)(smem + BOUNCE + (row + 8) * ROWB + e * 2) =
                        pack_h2(d[mtl][ntl][2], d[mtl][ntl][3]);
                }
            }
        }
        __syncthreads();

        // ---- bounce -> gmem B-fragment layout (coalesced STG.32) ----
        {
            uint32_t* Ub = U_scratch + (size_t)bk * 8192;
            #pragma unroll
            for (int w = 0; w < 8; w++) {
                int idx = w * 256 + t;             // 0..2047 local words
                int r   = idx & 1;
                int ln  = (idx >> 1) & 31;
                int nt  = (idx >> 6) & 7;
                int ktl = (idx >> 9) & 3;
                int jl  = ktl * 16 + (ln & 3) * 2 + r * 8;
                int e   = nt * 8 + (ln >> 2);
                uint16_t h0 = *(const uint16_t*)(smem + BOUNCE + jl * ROWB + e * 2);
                uint16_t h1 = *(const uint16_t*)(smem + BOUNCE + (jl + 1) * ROWB + e * 2);
                uint32_t word = (uint32_t)h0 | ((uint32_t)h1 << 16);
                int ktg = (j0 >> 4) + ktl;
                Ub[((ktg * 8 + nt) * 32 + ln) * 2 + r] = word;
            }
        }
        __syncthreads();
    }
}

// ---------------------------------------------------------------------------
// Kernel 3: fp16 mma attention. A staged once (fp16 frags); B (U frags)
// cp.async double-buffered; epilogue fp32.
// ---------------------------------------------------------------------------
#define AT_A  0
#define AT_B0 34816
#define AT_B1 67584
#define AT_SMEM 100352

__global__ void __launch_bounds__(256, 2)
attn_mma_kernel(const float* __restrict__ rc, const float* __restrict__ rq,
                const float* __restrict__ attc, const float* __restrict__ attq,
                float* __restrict__ out) {
    extern __shared__ char smem[];
    const uint32_t smem_base = smem_u32(smem);
    const int t = threadIdx.x;
    const int x = blockIdx.x;
    const int kg  = x & 15;
    const int Mq  = (x >> 4) & 3;
    const int map = (x >> 6) & 1;
    const int b   = x >> 7;

    const int wid  = t >> 5;
    const int lane = t & 31;
    const int wm = wid >> 2;
    const int wn = wid & 3;

    const int k0 = kg * 16;

    // ---- Kick off B stage for k0 into buf0 (async, 32KB) ----
    {
        const char* src = (const char*)(U_scratch + ((size_t)(b * C_ + k0)) * 8192);
        #pragma unroll
        for (int it = 0; it < 8; it++) {
            int o = (it * 256 + t) * 16;
            cp_async16(smem_base + AT_B0 + o, src + o);
        }
        cp_commit();
    }

    // ---- Stage A once: 64 rows x 256 j, fp16 frag-major ----
    {
        const float* att = (map ? attq : attc) + (size_t)b * C_ * C_ + (size_t)(Mq * 64) * C_;
        #pragma unroll 4
        for (int it = 0; it < 16; it++) {
            int idx = it * 256 + t;
            int i  = idx >> 6;
            int j0 = (idx & 63) * 4;
            float4 v = *(const float4*)&att[(size_t)i * C_ + j0];
            int mt = i >> 4, kt = j0 >> 4;
            int reg = ((i >> 3) & 1) | (((j0 >> 3) & 1) << 1);
            int lp  = (i & 7) * 4 + ((j0 & 7) >> 1);
            uint2 w;
            w.x = pack_h2(v.x, v.y);
            w.y = pack_h2(v.z, v.w);
            *(uint2*)(smem + AT_A + (mt * 16 + kt) * TILES + reg * REGS + lp * 4) = w;
        }
    }
    cp_wait0();
    __syncthreads();

    float* outbase = out + (map ? (size_t)B_ * C_ * C_ * E_ : 0);
    const float* residbase = map ? rq : rc;

    uint32_t bufoff = AT_B0;
    #pragma unroll 1
    for (int kk = 0; kk < 16; kk++) {
        const int k = k0 + kk;

        if (kk < 15) {
            const char* src = (const char*)(U_scratch + ((size_t)(b * C_ + k + 1)) * 8192);
            uint32_t dst = smem_base + (bufoff ^ (AT_B0 ^ AT_B1));
            #pragma unroll
            for (int it = 0; it < 8; it++) {
                int o = (it * 256 + t) * 16;
                cp_async16(dst + o, src + o);
            }
            cp_commit();
        }

        // ---- mma mainloop: D[64x64] += A[64x256] * B[256x64], 16 kt ----
        float d[2][2][4];
        #pragma unroll
        for (int i0 = 0; i0 < 2; i0++)
            #pragma unroll
            for (int i1 = 0; i1 < 2; i1++)
                #pragma unroll
                for (int i2 = 0; i2 < 4; i2++) d[i0][i1][i2] = 0.0f;

        #pragma unroll 4
        for (int kt = 0; kt < 16; kt++) {
            uint32_t a[2][4];
            #pragma unroll
            for (int mtl = 0; mtl < 2; mtl++) {
                const char* base = smem + AT_A + ((wm * 2 + mtl) * 16 + kt) * TILES + lane * 4;
                a[mtl][0] = *(const uint32_t*)(base);
                a[mtl][1] = *(const uint32_t*)(base + REGS);
                a[mtl][2] = *(const uint32_t*)(base + 2 * REGS);
                a[mtl][3] = *(const uint32_t*)(base + 3 * REGS);
            }
            uint32_t bw[2][2];
            #pragma unroll
            for (int ntl = 0; ntl < 2; ntl++) {
                int nt = wn * 2 + ntl;
                uint2 bv = *(const uint2*)(smem + bufoff + ((kt * 8 + nt) * 32 + lane) * 8);
                bw[ntl][0] = bv.x; bw[ntl][1] = bv.y;
            }
            #pragma unroll
            for (int mtl = 0; mtl < 2; mtl++)
                #pragma unroll
                for (int ntl = 0; ntl < 2; ntl++)
                    mma_f16(d[mtl][ntl], a[mtl], bw[ntl]);
        }

        // ---- epilogue: out = resid - ALPHA * D (fp32) ----
        {
            const float* resid = residbase + ((size_t)(b * C_ + k) * C_) * E_;
            float* o = outbase + ((size_t)(b * C_ + k) * C_) * E_;
            #pragma unroll
            for (int mtl = 0; mtl < 2; mtl++) {
                int row = Mq * 64 + wm * 32 + mtl * 16 + (lane >> 2);
                #pragma unroll
                for (int ntl = 0; ntl < 2; ntl++) {
                    int e = wn * 16 + ntl * 8 + (lane & 3) * 2;
                    float2 rA = *(const float2*)&resid[(size_t)row * E_ + e];
                    float2 rB = *(const float2*)&resid[(size_t)(row + 8) * E_ + e];
                    float2 oA, oB;
                    oA.x = rA.x - ALPHA * d[mtl][ntl][0];
                    oA.y = rA.y - ALPHA * d[mtl][ntl][1];
                    oB.x = rB.x - ALPHA * d[mtl][ntl][2];
                    oB.y = rB.y - ALPHA * d[mtl][ntl][3];
                    *(float2*)&o[(size_t)row * E_ + e]       = oA;
                    *(float2*)&o[(size_t)(row + 8) * E_ + e] = oB;
                }
            }
        }

        if (kk < 15) {
            cp_wait0();
            __syncthreads();
            bufoff ^= (AT_B0 ^ AT_B1);
        }
    }
}

// ---------------------------------------------------------------------------
// Launch
// ---------------------------------------------------------------------------
extern "C" void kernel_launch(void* const* d_in, const int* in_sizes, int n_in,
                              void* d_out, int out_size) {
    const float* x    = (const float*)d_in[0];
    const float* y    = (const float*)d_in[1];
    const float* rc   = (const float*)d_in[2];
    const float* rq   = (const float*)d_in[3];
    const float* attc = (const float*)d_in[4];
    const float* attq = (const float*)d_in[5];
    const float* W1   = (const float*)d_in[6];
    const float* b1   = (const float*)d_in[7];
    const float* W2   = (const float*)d_in[8];
    const float* b2   = (const float*)d_in[9];
    const float* W3   = (const float*)d_in[10];
    const float* b3   = (const float*)d_in[11];
    float* out = (float*)d_out;

    cudaFuncSetAttribute(mlp_tc_kernel,   cudaFuncAttributeMaxDynamicSharedMemorySize, MLP_SMEM_B);
    cudaFuncSetAttribute(attn_mma_kernel, cudaFuncAttributeMaxDynamicSharedMemorySize, AT_SMEM);

    p_kernel<<<B_ * C_, H_>>>(x, y, W1, b1);
    mlp_tc_kernel<<<296, 256, MLP_SMEM_B>>>(rc, W1, b2, W2, W3, b3);
    attn_mma_kernel<<<512, 256, AT_SMEM>>>(rc, rq, attc, attq, out);
}